// round 6
// baseline (speedup 1.0000x reference)
#include <cuda_runtime.h>
#include <math.h>

#define TT 100
#define BB 128
#define HH 512
#define GG 2048            // 4*H
#define NIN 128            // rnn input dim
#define NITEMS 10000
#define KL 544             // H + SDIM
#define NPN 128000000      // TT*BB*NITEMS

typedef unsigned long long ull;

// ---------------- static device scratch (no runtime allocation) ----------------
__device__ float g_ars[TT * BB * NIN];       // [12800,128] built input
__device__ float g_xproj[TT * BB * GG];      // [12800,2048]
__device__ float g_linin[TT * BB * KL];      // [12800,544]  (h | stat)
__device__ float g_h[2][BB * HH];            // ping-pong hidden
__device__ float g_c[BB * HH];               // cell state
__device__ float g_l2[2];                    // sumsq(W_lin), sumsq(b_lin)

// ---------------- f32x2 helpers (2x fp32 FMA throughput on sm_103a) ------------
__device__ __forceinline__ ull pack2(float x, float y) {
    ull v; asm("mov.b64 %0,{%1,%2};" : "=l"(v) : "f"(x), "f"(y)); return v;
}
__device__ __forceinline__ float2 unpack2(ull v) {
    float2 f; asm("mov.b64 {%0,%1},%2;" : "=f"(f.x), "=f"(f.y) : "l"(v)); return f;
}
__device__ __forceinline__ void fma2(ull &c, ull a, ull b) {
    asm("fma.rn.f32x2 %0,%1,%2,%3;" : "=l"(c) : "l"(a), "l"(b), "l"(c));
}
__device__ __forceinline__ float sigf(float x) { return 1.0f / (1.0f + expf(-x)); }

// ================= init: hx,cx -> scratch =================
__global__ void k_init(const float* __restrict__ hx, const float* __restrict__ cx) {
    int i = blockIdx.x * blockDim.x + threadIdx.x;
    if (i < BB * HH) { g_h[0][i] = hx[i]; g_c[i] = cx[i]; }
}

// ================= build ars = [emb | one_hot | stat] =================
__global__ void k_ars(const int* __restrict__ act, const float* __restrict__ rew,
                      const float* __restrict__ stat, const float* __restrict__ emb) {
    int idx = blockIdx.x * blockDim.x + threadIdx.x;   // over 12800*32 float4s
    if (idx >= TT * BB * 32) return;
    int tb = idx >> 5;
    int k = (idx & 31) * 4;
    float4 v;
    if (k < 64) {
        v = *(const float4*)&emb[(size_t)act[tb] * 64 + k];
    } else if (k < 96) {
        float r = rew[tb];
        int ri = (int)floorf((32.0f * (2.0f - r)) / 4.0f);   // bit-matches reference
        int kb = k - 64;
        v.x = (ri == kb    ) ? 1.f : 0.f;
        v.y = (ri == kb + 1) ? 1.f : 0.f;
        v.z = (ri == kb + 2) ? 1.f : 0.f;
        v.w = (ri == kb + 3) ? 1.f : 0.f;
    } else {
        v = *(const float4*)&stat[(size_t)tb * 32 + (k - 96)];
    }
    *(float4*)&g_ars[(size_t)tb * NIN + k] = v;
}

// ================= x_proj = ars @ W_ih^T + b_ih + b_hh =================
// M=12800, N=2048, K=128. BM=64, BN=64, BK=16, 256 thr, 4x4/thread.
__global__ __launch_bounds__(256) void k_xproj(
    const float* __restrict__ W_ih, const float* __restrict__ b_ih,
    const float* __restrict__ b_hh)
{
    __shared__ float A_s[16][65];
    __shared__ float B_s[16][65];
    const int tid = threadIdx.x;
    const int g0  = blockIdx.x * 64;
    const int tb0 = blockIdx.y * 64;
    const int tx = tid & 15;     // rows tx*4..+3
    const int ty = tid >> 4;     // cols ty*4..+3

    float acc[4][4];
    #pragma unroll
    for (int i = 0; i < 4; i++)
        #pragma unroll
        for (int j = 0; j < 4; j++) acc[i][j] = 0.f;

    for (int k0 = 0; k0 < NIN; k0 += 16) {
        __syncthreads();
        {
            int m = tid >> 2, k4 = tid & 3;
            float4 va = *(const float4*)&g_ars[(size_t)(tb0 + m) * NIN + k0 + k4 * 4];
            A_s[k4 * 4 + 0][m] = va.x; A_s[k4 * 4 + 1][m] = va.y;
            A_s[k4 * 4 + 2][m] = va.z; A_s[k4 * 4 + 3][m] = va.w;
            float4 vb = *(const float4*)&W_ih[(size_t)(g0 + m) * NIN + k0 + k4 * 4];
            B_s[k4 * 4 + 0][m] = vb.x; B_s[k4 * 4 + 1][m] = vb.y;
            B_s[k4 * 4 + 2][m] = vb.z; B_s[k4 * 4 + 3][m] = vb.w;
        }
        __syncthreads();
        #pragma unroll
        for (int k = 0; k < 16; k++) {
            float a[4], b[4];
            #pragma unroll
            for (int i = 0; i < 4; i++) a[i] = A_s[k][tx * 4 + i];
            #pragma unroll
            for (int j = 0; j < 4; j++) b[j] = B_s[k][ty * 4 + j];
            #pragma unroll
            for (int i = 0; i < 4; i++)
                #pragma unroll
                for (int j = 0; j < 4; j++) acc[i][j] = fmaf(a[i], b[j], acc[i][j]);
        }
    }
    float bs[4];
    #pragma unroll
    for (int j = 0; j < 4; j++) {
        int g = g0 + ty * 4 + j;
        bs[j] = b_ih[g] + b_hh[g];
    }
    #pragma unroll
    for (int i = 0; i < 4; i++) {
        int row = tb0 + tx * 4 + i;
        float4 o = make_float4(acc[i][0] + bs[0], acc[i][1] + bs[1],
                               acc[i][2] + bs[2], acc[i][3] + bs[3]);
        *(float4*)&g_xproj[(size_t)row * GG + g0 + ty * 4] = o;
    }
}

// ================= statcopy: lin_in[:,512:544] = stat =================
__global__ void k_statcopy(const float* __restrict__ stat) {
    int i4 = blockIdx.x * blockDim.x + threadIdx.x;   // over 12800*8 float4s
    if (i4 < TT * BB * 8) {
        int tb = i4 >> 3, s4 = i4 & 7;
        float4 v = *(const float4*)&stat[(size_t)tb * 32 + s4 * 4];
        *(float4*)&g_linin[(size_t)tb * KL + HH + s4 * 4] = v;
    }
}

// ================= one LSTM step =================
// gates[b,g] = xproj[t,b,g] + h_prev[b,:] . W_hh[g,:]; apply cell; h -> g_h[dst], g_linin
// grid (32,4): bx -> 16 h-cols (all 4 gates -> 64 gate cols), by -> 32 batch rows.
__global__ __launch_bounds__(256) void k_lstm(const float* __restrict__ W_hh, int t, int src)
{
    __shared__ float h_s[32][33];
    __shared__ float w_s[32][65];
    __shared__ float gs[32][65];

    const int tid = threadIdx.x;
    const int m0 = blockIdx.x * 16;
    const int r0 = blockIdx.y * 32;
    const int tx = tid & 15;      // rows tx*2, tx*2+1 (local)
    const int ty = tid >> 4;      // cols ty*4..+3 (of 64)
    const float* __restrict__ hsrc = g_h[src];
    const int dst = src ^ 1;

    float acc[2][4];
    #pragma unroll
    for (int i = 0; i < 2; i++)
        #pragma unroll
        for (int j = 0; j < 4; j++) acc[i][j] = 0.f;

    for (int kk0 = 0; kk0 < HH; kk0 += 32) {
        __syncthreads();
        {   // h tile: h_s[k][r] (transposed), 256 float4
            int r = tid >> 3, k4 = tid & 7;
            float4 v = *(const float4*)&hsrc[(size_t)(r0 + r) * HH + kk0 + k4 * 4];
            h_s[k4 * 4 + 0][r] = v.x; h_s[k4 * 4 + 1][r] = v.y;
            h_s[k4 * 4 + 2][r] = v.z; h_s[k4 * 4 + 3][r] = v.w;
        }
        #pragma unroll
        for (int i = 0; i < 2; i++) {  // W tile: w_s[k][c], 512 float4
            int idx = tid + i * 256;
            int c = idx >> 3, k4 = idx & 7;
            int gcol = (c >> 4) * HH + m0 + (c & 15);
            float4 v = *(const float4*)&W_hh[(size_t)gcol * HH + kk0 + k4 * 4];
            w_s[k4 * 4 + 0][c] = v.x; w_s[k4 * 4 + 1][c] = v.y;
            w_s[k4 * 4 + 2][c] = v.z; w_s[k4 * 4 + 3][c] = v.w;
        }
        __syncthreads();
        #pragma unroll
        for (int k = 0; k < 32; k++) {
            float a0 = h_s[k][tx * 2], a1 = h_s[k][tx * 2 + 1];
            #pragma unroll
            for (int j = 0; j < 4; j++) {
                float b = w_s[k][ty * 4 + j];
                acc[0][j] = fmaf(a0, b, acc[0][j]);
                acc[1][j] = fmaf(a1, b, acc[1][j]);
            }
        }
    }
    // add x-projection, stage gates in SMEM
    __syncthreads();
    #pragma unroll
    for (int rr = 0; rr < 2; rr++) {
        int r = tx * 2 + rr;
        size_t base = ((size_t)t * BB + r0 + r) * GG;
        #pragma unroll
        for (int j = 0; j < 4; j++) {
            int c = ty * 4 + j;
            int gcol = (c >> 4) * HH + m0 + (c & 15);
            gs[r][c] = acc[rr][j] + g_xproj[base + gcol];
        }
    }
    __syncthreads();
    // cell update: 512 (b,m) pairs, 2 per thread
    #pragma unroll
    for (int e = 0; e < 2; e++) {
        int p = tid * 2 + e;
        int r = p >> 4, mi = p & 15;
        float gi = gs[r][mi];
        float gf = gs[r][16 + mi];
        float gg = gs[r][32 + mi];
        float go = gs[r][48 + mi];
        int b = r0 + r, m = m0 + mi;
        int ci = b * HH + m;
        float cn = sigf(gf) * g_c[ci] + sigf(gi) * tanhf(gg);
        float h = sigf(go) * tanhf(cn);
        g_c[ci] = cn;
        g_h[dst][ci] = h;
        g_linin[((size_t)t * BB + b) * KL + m] = h;
    }
}

// ================= final linear: out = lin_in @ W_lin^T + b_lin =================
// M=12800, N=10000, K=544. BM=128, BN=64, BK=16, 256 thr, f32x2 row-pairs (8x4/thread).
__global__ __launch_bounds__(256) void k_lin(
    const float* __restrict__ W_lin, const float* __restrict__ b_lin,
    float* __restrict__ out)
{
    __shared__ float A_s[16][128];
    __shared__ float B_s[16][68];
    const int tid = threadIdx.x;
    const int v0  = blockIdx.x * 64;
    const int tb0 = blockIdx.y * 128;
    const int tx = tid & 15;    // rows tx*8..+7 (4 pairs)
    const int ty = tid >> 4;    // cols ty*4..+3

    ull acc[4][4];
    #pragma unroll
    for (int i = 0; i < 4; i++)
        #pragma unroll
        for (int j = 0; j < 4; j++) acc[i][j] = 0ull;

    for (int k0 = 0; k0 < KL; k0 += 16) {
        __syncthreads();
        #pragma unroll
        for (int i = 0; i < 2; i++) {  // A tile: 512 float4, transposed
            int idx = tid + i * 256;
            int m = idx >> 2, k4 = idx & 3;
            float4 v = *(const float4*)&g_linin[(size_t)(tb0 + m) * KL + k0 + k4 * 4];
            A_s[k4 * 4 + 0][m] = v.x; A_s[k4 * 4 + 1][m] = v.y;
            A_s[k4 * 4 + 2][m] = v.z; A_s[k4 * 4 + 3][m] = v.w;
        }
        {   // B tile: 256 float4, transposed, guarded
            int c = tid >> 2, k4 = tid & 3;
            int v = v0 + c;
            float4 w = make_float4(0.f, 0.f, 0.f, 0.f);
            if (v < NITEMS) w = *(const float4*)&W_lin[(size_t)v * KL + k0 + k4 * 4];
            B_s[k4 * 4 + 0][c] = w.x; B_s[k4 * 4 + 1][c] = w.y;
            B_s[k4 * 4 + 2][c] = w.z; B_s[k4 * 4 + 3][c] = w.w;
        }
        __syncthreads();
        #pragma unroll
        for (int k = 0; k < 16; k++) {
            ull a0 = *(const ull*)&A_s[k][tx * 8 + 0];
            ull a1 = *(const ull*)&A_s[k][tx * 8 + 2];
            ull a2 = *(const ull*)&A_s[k][tx * 8 + 4];
            ull a3 = *(const ull*)&A_s[k][tx * 8 + 6];
            float4 w = *(const float4*)&B_s[k][ty * 4];
            ull b0 = pack2(w.x, w.x), b1 = pack2(w.y, w.y);
            ull b2 = pack2(w.z, w.z), b3 = pack2(w.w, w.w);
            fma2(acc[0][0], a0, b0); fma2(acc[0][1], a0, b1); fma2(acc[0][2], a0, b2); fma2(acc[0][3], a0, b3);
            fma2(acc[1][0], a1, b0); fma2(acc[1][1], a1, b1); fma2(acc[1][2], a1, b2); fma2(acc[1][3], a1, b3);
            fma2(acc[2][0], a2, b0); fma2(acc[2][1], a2, b1); fma2(acc[2][2], a2, b2); fma2(acc[2][3], a2, b3);
            fma2(acc[3][0], a3, b0); fma2(acc[3][1], a3, b1); fma2(acc[3][2], a3, b2); fma2(acc[3][3], a3, b3);
        }
    }
    // epilogue
    float bl[4];
    bool full4 = (v0 + ty * 4 + 4 <= NITEMS);
    #pragma unroll
    for (int j = 0; j < 4; j++) {
        int v = v0 + ty * 4 + j;
        bl[j] = (v < NITEMS) ? b_lin[v] : 0.f;
    }
    #pragma unroll
    for (int rp = 0; rp < 4; rp++) {
        float2 c0 = unpack2(acc[rp][0]), c1 = unpack2(acc[rp][1]);
        float2 c2 = unpack2(acc[rp][2]), c3 = unpack2(acc[rp][3]);
        int row = tb0 + tx * 8 + rp * 2;
        float4 lo = make_float4(c0.x + bl[0], c1.x + bl[1], c2.x + bl[2], c3.x + bl[3]);
        float4 hi = make_float4(c0.y + bl[0], c1.y + bl[1], c2.y + bl[2], c3.y + bl[3]);
        size_t o0 = (size_t)row * NITEMS + v0 + ty * 4;
        size_t o1 = (size_t)(row + 1) * NITEMS + v0 + ty * 4;
        if (full4) {
            *(float4*)&out[o0] = lo;
            *(float4*)&out[o1] = hi;
        } else {
            float lof[4] = {lo.x, lo.y, lo.z, lo.w};
            float hif[4] = {hi.x, hi.y, hi.z, hi.w};
            #pragma unroll
            for (int j = 0; j < 4; j++)
                if (v0 + ty * 4 + j < NITEMS) { out[o0 + j] = lof[j]; out[o1 + j] = hif[j]; }
        }
    }
}

// ================= l2 norm =================
__global__ void k_l2zero() { if (threadIdx.x < 2) g_l2[threadIdx.x] = 0.f; }

__global__ void k_l2reduce(const float* __restrict__ W_lin, const float* __restrict__ b_lin) {
    __shared__ float sh[256];
    int tid = threadIdx.x;
    int stride = gridDim.x * blockDim.x;
    float sw = 0.f;
    for (size_t i = blockIdx.x * blockDim.x + tid; i < (size_t)NITEMS * KL; i += stride) {
        float v = W_lin[i]; sw += v * v;
    }
    float sb = 0.f;
    for (int i = blockIdx.x * blockDim.x + tid; i < NITEMS; i += stride) {
        float v = b_lin[i]; sb += v * v;
    }
    sh[tid] = sw; __syncthreads();
    for (int s = 128; s > 0; s >>= 1) { if (tid < s) sh[tid] += sh[tid + s]; __syncthreads(); }
    if (tid == 0) atomicAdd(&g_l2[0], sh[0]);
    __syncthreads();
    sh[tid] = sb; __syncthreads();
    for (int s = 128; s > 0; s >>= 1) { if (tid < s) sh[tid] += sh[tid + s]; __syncthreads(); }
    if (tid == 0) atomicAdd(&g_l2[1], sh[0]);
}

__global__ void k_l2final(float* __restrict__ out, int has_scalar) {
    if (has_scalar && threadIdx.x == 0)
        out[NPN] = sqrtf(g_l2[0]) + sqrtf(g_l2[1]);
}

// ================= launch =================
extern "C" void kernel_launch(void* const* d_in, const int* in_sizes, int n_in,
                              void* d_out, int out_size) {
    const int*   act   = (const int*)  d_in[0];
    const float* rew   = (const float*)d_in[1];
    const float* stat  = (const float*)d_in[2];
    const float* hx    = (const float*)d_in[3];
    const float* cx    = (const float*)d_in[4];
    const float* emb   = (const float*)d_in[5];
    const float* W_ih  = (const float*)d_in[6];
    const float* W_hh  = (const float*)d_in[7];
    const float* b_ih  = (const float*)d_in[8];
    const float* b_hh  = (const float*)d_in[9];
    const float* W_lin = (const float*)d_in[10];
    const float* b_lin = (const float*)d_in[11];
    float* out = (float*)d_out;

    k_init<<<(BB * HH + 255) / 256, 256>>>(hx, cx);
    k_ars<<<(TT * BB * 32 + 255) / 256, 256>>>(act, rew, stat, emb);
    k_statcopy<<<(TT * BB * 8 + 255) / 256, 256>>>(stat);
    k_xproj<<<dim3(GG / 64, TT * BB / 64), 256>>>(W_ih, b_ih, b_hh);

    for (int t = 0; t < TT; t++)
        k_lstm<<<dim3(HH / 16, BB / 32), 256>>>(W_hh, t, t & 1);

    k_lin<<<dim3((NITEMS + 63) / 64, TT * BB / 128), 256>>>(W_lin, b_lin, out);

    k_l2zero<<<1, 32>>>();
    k_l2reduce<<<512, 256>>>(W_lin, b_lin);
    k_l2final<<<1, 32>>>(out, out_size > NPN ? 1 : 0);
}

// round 7
// speedup vs baseline: 1.1057x; 1.1057x over previous
#include <cuda_runtime.h>
#include <math.h>

#define TT 100
#define BB 128
#define HH 512
#define GG 2048            // 4*H
#define NIN 128            // rnn input dim
#define NITEMS 10000
#define KL 544             // H + SDIM
#define NPN 128000000      // TT*BB*NITEMS

typedef unsigned long long ull;

// ---------------- static device scratch (no runtime allocation) ----------------
__device__ float g_ars[TT * BB * NIN];       // [12800,128] built input
__device__ float g_xproj[TT * BB * GG];      // [12800,2048]
__device__ float g_linin[TT * BB * KL];      // [12800,544]  (h | stat)
__device__ float g_h[2][BB * HH];            // ping-pong hidden
__device__ float g_c[BB * HH];               // cell state
__device__ float g_l2[2];                    // sumsq(W_lin), sumsq(b_lin)

// ---------------- f32x2 helpers (2x fp32 FMA throughput on sm_103a) ------------
__device__ __forceinline__ ull pack2(float x, float y) {
    ull v; asm("mov.b64 %0,{%1,%2};" : "=l"(v) : "f"(x), "f"(y)); return v;
}
__device__ __forceinline__ float2 unpack2(ull v) {
    float2 f; asm("mov.b64 {%0,%1},%2;" : "=f"(f.x), "=f"(f.y) : "l"(v)); return f;
}
__device__ __forceinline__ void fma2(ull &c, ull a, ull b) {
    asm("fma.rn.f32x2 %0,%1,%2,%3;" : "=l"(c) : "l"(a), "l"(b), "l"(c));
}
__device__ __forceinline__ float sigf(float x) { return 1.0f / (1.0f + expf(-x)); }

// ================= init: hx,cx -> scratch =================
__global__ void k_init(const float* __restrict__ hx, const float* __restrict__ cx) {
    int i = blockIdx.x * blockDim.x + threadIdx.x;
    if (i < BB * HH) { g_h[0][i] = hx[i]; g_c[i] = cx[i]; }
}

// ================= build ars = [emb | one_hot | stat] =================
__global__ void k_ars(const int* __restrict__ act, const float* __restrict__ rew,
                      const float* __restrict__ stat, const float* __restrict__ emb) {
    int idx = blockIdx.x * blockDim.x + threadIdx.x;   // over 12800*32 float4s
    if (idx >= TT * BB * 32) return;
    int tb = idx >> 5;
    int k = (idx & 31) * 4;
    float4 v;
    if (k < 64) {
        v = *(const float4*)&emb[(size_t)act[tb] * 64 + k];
    } else if (k < 96) {
        float r = rew[tb];
        int ri = (int)floorf((32.0f * (2.0f - r)) / 4.0f);   // bit-matches reference
        int kb = k - 64;
        v.x = (ri == kb    ) ? 1.f : 0.f;
        v.y = (ri == kb + 1) ? 1.f : 0.f;
        v.z = (ri == kb + 2) ? 1.f : 0.f;
        v.w = (ri == kb + 3) ? 1.f : 0.f;
    } else {
        v = *(const float4*)&stat[(size_t)tb * 32 + (k - 96)];
    }
    *(float4*)&g_ars[(size_t)tb * NIN + k] = v;
}

// ================= statcopy: lin_in[:,512:544] = stat =================
__global__ void k_statcopy(const float* __restrict__ stat) {
    int i4 = blockIdx.x * blockDim.x + threadIdx.x;   // over 12800*8 float4s
    if (i4 < TT * BB * 8) {
        int tb = i4 >> 3, s4 = i4 & 7;
        float4 v = *(const float4*)&stat[(size_t)tb * 32 + s4 * 4];
        *(float4*)&g_linin[(size_t)tb * KL + HH + s4 * 4] = v;
    }
}

// ================= x_proj = ars @ W_ih^T + b_ih + b_hh ==================
// M=12800, N=2048, K=128. BM=128, BN=128, BK=8, 256 thr, 8x8/thread (f32x2 pairs).
__global__ __launch_bounds__(256, 2) void k_xproj(
    const float* __restrict__ W_ih, const float* __restrict__ b_ih,
    const float* __restrict__ b_hh)
{
    __shared__ __align__(16) float A_s[8][132];
    __shared__ __align__(16) float B2_s[8][264];
    const int tid = threadIdx.x;
    const int g0  = blockIdx.x * 128;
    const int tb0 = blockIdx.y * 128;
    const int tx = tid & 15;    // rows tx*8..+7
    const int ty = tid >> 4;    // cols ty*8..+7
    const int mf = tid >> 1;            // fill row/col 0..127
    const int kf = (tid & 1) * 4;       // fill k offset 0 or 4

    ull acc[4][8];
    #pragma unroll
    for (int i = 0; i < 4; i++)
        #pragma unroll
        for (int j = 0; j < 8; j++) acc[i][j] = 0ull;

    // prefetch tile 0
    float4 rA = *(const float4*)&g_ars[(size_t)(tb0 + mf) * NIN + kf];
    float4 rB = *(const float4*)&W_ih[(size_t)(g0 + mf) * NIN + kf];

    for (int kt = 0; kt < NIN / 8; kt++) {
        A_s[kf + 0][mf] = rA.x; A_s[kf + 1][mf] = rA.y;
        A_s[kf + 2][mf] = rA.z; A_s[kf + 3][mf] = rA.w;
        *(ull*)&B2_s[kf + 0][2 * mf] = pack2(rB.x, rB.x);
        *(ull*)&B2_s[kf + 1][2 * mf] = pack2(rB.y, rB.y);
        *(ull*)&B2_s[kf + 2][2 * mf] = pack2(rB.z, rB.z);
        *(ull*)&B2_s[kf + 3][2 * mf] = pack2(rB.w, rB.w);
        __syncthreads();
        if (kt + 1 < NIN / 8) {
            int k0n = (kt + 1) * 8;
            rA = *(const float4*)&g_ars[(size_t)(tb0 + mf) * NIN + k0n + kf];
            rB = *(const float4*)&W_ih[(size_t)(g0 + mf) * NIN + k0n + kf];
        }
        #pragma unroll
        for (int k = 0; k < 8; k++) {
            ulonglong2 a01 = *(const ulonglong2*)&A_s[k][tx * 8];
            ulonglong2 a23 = *(const ulonglong2*)&A_s[k][tx * 8 + 4];
            ull a[4] = {a01.x, a01.y, a23.x, a23.y};
            #pragma unroll
            for (int jh = 0; jh < 2; jh++) {
                ulonglong2 b01 = *(const ulonglong2*)&B2_s[k][ty * 16 + jh * 8];
                ulonglong2 b23 = *(const ulonglong2*)&B2_s[k][ty * 16 + jh * 8 + 4];
                ull b[4] = {b01.x, b01.y, b23.x, b23.y};
                #pragma unroll
                for (int i = 0; i < 4; i++)
                    #pragma unroll
                    for (int j = 0; j < 4; j++)
                        fma2(acc[i][jh * 4 + j], a[i], b[j]);
            }
        }
        __syncthreads();
    }
    // epilogue with biases
    float bs[8];
    #pragma unroll
    for (int j = 0; j < 8; j++) {
        int g = g0 + ty * 8 + j;
        bs[j] = b_ih[g] + b_hh[g];
    }
    #pragma unroll
    for (int rp = 0; rp < 4; rp++) {
        float lo[8], hi[8];
        #pragma unroll
        for (int j = 0; j < 8; j++) {
            float2 c = unpack2(acc[rp][j]);
            lo[j] = c.x + bs[j]; hi[j] = c.y + bs[j];
        }
        int row = tb0 + tx * 8 + rp * 2;
        size_t o0 = (size_t)row * GG + g0 + ty * 8;
        *(float4*)&g_xproj[o0]          = make_float4(lo[0], lo[1], lo[2], lo[3]);
        *(float4*)&g_xproj[o0 + 4]      = make_float4(lo[4], lo[5], lo[6], lo[7]);
        *(float4*)&g_xproj[o0 + GG]     = make_float4(hi[0], hi[1], hi[2], hi[3]);
        *(float4*)&g_xproj[o0 + GG + 4] = make_float4(hi[4], hi[5], hi[6], hi[7]);
    }
}

// ================= one LSTM step (f32x2 row-pairs, dup-W SMEM) =================
// gates[b,g] = xproj[t,b,g] + h_prev[b,:] . W_hh[g,:]; apply cell.
// grid (32,4) = 128 blocks: 16 h-cols (x4 gates = 64 gate cols) x 32 batch rows.
// 256 thr; thread tile = 4 rows (2 f32x2 pairs) x 2 cols.
__global__ __launch_bounds__(256) void k_lstm(const float* __restrict__ W_hh, int t, int src)
{
    __shared__ __align__(16) float h_s[32][34];    // [k][r], r-pairs contiguous
    __shared__ __align__(16) float w2_s[32][132];  // [k][2c] duplicated weights
    __shared__ float gs[32][65];

    const int tid = threadIdx.x;
    const int m0 = blockIdx.x * 16;
    const int r0 = blockIdx.y * 32;
    const int tx = tid & 7;       // rows tx*4..+3
    const int ty = tid >> 3;      // cols ty*2, ty*2+1 (of 64)
    const float* __restrict__ hsrc = g_h[src];
    const int dst = src ^ 1;

    ull acc[2][2];
    acc[0][0] = acc[0][1] = acc[1][0] = acc[1][1] = 0ull;

    for (int kk0 = 0; kk0 < HH; kk0 += 32) {
        __syncthreads();
        {   // h tile: transposed, h_s[k][r]
            int r = tid >> 3, k4 = tid & 7;
            float4 v = *(const float4*)&hsrc[(size_t)(r0 + r) * HH + kk0 + k4 * 4];
            h_s[k4 * 4 + 0][r] = v.x; h_s[k4 * 4 + 1][r] = v.y;
            h_s[k4 * 4 + 2][r] = v.z; h_s[k4 * 4 + 3][r] = v.w;
        }
        #pragma unroll
        for (int i = 0; i < 2; i++) {  // W tile duplicated: w2_s[k][2c],[2c+1]
            int idx = tid + i * 256;
            int c = idx >> 3, k4 = idx & 7;
            int gcol = (c >> 4) * HH + m0 + (c & 15);
            float4 v = *(const float4*)&W_hh[(size_t)gcol * HH + kk0 + k4 * 4];
            *(ull*)&w2_s[k4 * 4 + 0][2 * c] = pack2(v.x, v.x);
            *(ull*)&w2_s[k4 * 4 + 1][2 * c] = pack2(v.y, v.y);
            *(ull*)&w2_s[k4 * 4 + 2][2 * c] = pack2(v.z, v.z);
            *(ull*)&w2_s[k4 * 4 + 3][2 * c] = pack2(v.w, v.w);
        }
        __syncthreads();
        #pragma unroll
        for (int k = 0; k < 32; k++) {
            ull a0 = *(const ull*)&h_s[k][tx * 4];
            ull a1 = *(const ull*)&h_s[k][tx * 4 + 2];
            ulonglong2 b = *(const ulonglong2*)&w2_s[k][ty * 4];
            fma2(acc[0][0], a0, b.x); fma2(acc[0][1], a0, b.y);
            fma2(acc[1][0], a1, b.x); fma2(acc[1][1], a1, b.y);
        }
    }
    // add x-projection, stage gates in SMEM
    __syncthreads();
    #pragma unroll
    for (int pi = 0; pi < 2; pi++) {
        float2 v0 = unpack2(acc[pi][0]);
        float2 v1 = unpack2(acc[pi][1]);
        int r = tx * 4 + pi * 2;
        int c0 = ty * 2, c1 = ty * 2 + 1;
        int gcol0 = (c0 >> 4) * HH + m0 + (c0 & 15);
        int gcol1 = (c1 >> 4) * HH + m0 + (c1 & 15);
        size_t base = ((size_t)t * BB + r0 + r) * GG;
        gs[r][c0]     = v0.x + g_xproj[base + gcol0];
        gs[r + 1][c0] = v0.y + g_xproj[base + GG + gcol0];
        gs[r][c1]     = v1.x + g_xproj[base + gcol1];
        gs[r + 1][c1] = v1.y + g_xproj[base + GG + gcol1];
    }
    __syncthreads();
    // cell update: 512 (b,m) pairs, 2 per thread
    #pragma unroll
    for (int e = 0; e < 2; e++) {
        int p = tid * 2 + e;
        int r = p >> 4, mi = p & 15;
        float gi = gs[r][mi];
        float gf = gs[r][16 + mi];
        float gg = gs[r][32 + mi];
        float go = gs[r][48 + mi];
        int b = r0 + r, m = m0 + mi;
        int ci = b * HH + m;
        float cn = sigf(gf) * g_c[ci] + sigf(gi) * tanhf(gg);
        float h = sigf(go) * tanhf(cn);
        g_c[ci] = cn;
        g_h[dst][ci] = h;
        g_linin[((size_t)t * BB + b) * KL + m] = h;
    }
}

// ================= final linear: out = lin_in @ W_lin^T + b_lin =================
// M=12800, N=10000, K=544. BM=128, BN=128, BK=8, 256 thr, 8x8/thread f32x2,
// pre-duplicated B in SMEM, register-prefetch pipeline.
__global__ __launch_bounds__(256, 2) void k_lin(
    const float* __restrict__ W_lin, const float* __restrict__ b_lin,
    float* __restrict__ out)
{
    __shared__ __align__(16) float A_s[8][132];
    __shared__ __align__(16) float B2_s[8][264];
    const int tid = threadIdx.x;
    const int v0  = blockIdx.x * 128;
    const int tb0 = blockIdx.y * 128;
    const int tx = tid & 15;    // rows tx*8..+7 (4 pairs)
    const int ty = tid >> 4;    // cols ty*8..+7
    const int mf = tid >> 1;
    const int kf = (tid & 1) * 4;
    const int item = v0 + mf;

    ull acc[4][8];
    #pragma unroll
    for (int i = 0; i < 4; i++)
        #pragma unroll
        for (int j = 0; j < 8; j++) acc[i][j] = 0ull;

    float4 rA = *(const float4*)&g_linin[(size_t)(tb0 + mf) * KL + kf];
    float4 rB = (item < NITEMS) ? *(const float4*)&W_lin[(size_t)item * KL + kf]
                                : make_float4(0.f, 0.f, 0.f, 0.f);

    for (int kt = 0; kt < KL / 8; kt++) {
        A_s[kf + 0][mf] = rA.x; A_s[kf + 1][mf] = rA.y;
        A_s[kf + 2][mf] = rA.z; A_s[kf + 3][mf] = rA.w;
        *(ull*)&B2_s[kf + 0][2 * mf] = pack2(rB.x, rB.x);
        *(ull*)&B2_s[kf + 1][2 * mf] = pack2(rB.y, rB.y);
        *(ull*)&B2_s[kf + 2][2 * mf] = pack2(rB.z, rB.z);
        *(ull*)&B2_s[kf + 3][2 * mf] = pack2(rB.w, rB.w);
        __syncthreads();
        if (kt + 1 < KL / 8) {
            int k0n = (kt + 1) * 8;
            rA = *(const float4*)&g_linin[(size_t)(tb0 + mf) * KL + k0n + kf];
            rB = (item < NITEMS) ? *(const float4*)&W_lin[(size_t)item * KL + k0n + kf]
                                 : make_float4(0.f, 0.f, 0.f, 0.f);
        }
        #pragma unroll
        for (int k = 0; k < 8; k++) {
            ulonglong2 a01 = *(const ulonglong2*)&A_s[k][tx * 8];
            ulonglong2 a23 = *(const ulonglong2*)&A_s[k][tx * 8 + 4];
            ull a[4] = {a01.x, a01.y, a23.x, a23.y};
            #pragma unroll
            for (int jh = 0; jh < 2; jh++) {
                ulonglong2 b01 = *(const ulonglong2*)&B2_s[k][ty * 16 + jh * 8];
                ulonglong2 b23 = *(const ulonglong2*)&B2_s[k][ty * 16 + jh * 8 + 4];
                ull b[4] = {b01.x, b01.y, b23.x, b23.y};
                #pragma unroll
                for (int i = 0; i < 4; i++)
                    #pragma unroll
                    for (int j = 0; j < 4; j++)
                        fma2(acc[i][jh * 4 + j], a[i], b[j]);
            }
        }
        __syncthreads();
    }
    // epilogue
    float bl[8];
    #pragma unroll
    for (int j = 0; j < 8; j++) {
        int v = v0 + ty * 8 + j;
        bl[j] = (v < NITEMS) ? b_lin[v] : 0.f;
    }
    #pragma unroll
    for (int rp = 0; rp < 4; rp++) {
        float lo[8], hi[8];
        #pragma unroll
        for (int j = 0; j < 8; j++) {
            float2 c = unpack2(acc[rp][j]);
            lo[j] = c.x + bl[j]; hi[j] = c.y + bl[j];
        }
        int row = tb0 + tx * 8 + rp * 2;
        #pragma unroll
        for (int g = 0; g < 2; g++) {
            int cb = v0 + ty * 8 + g * 4;
            size_t o0 = (size_t)row * NITEMS + cb;
            size_t o1 = o0 + NITEMS;
            if (cb + 4 <= NITEMS) {
                *(float4*)&out[o0] = make_float4(lo[g*4], lo[g*4+1], lo[g*4+2], lo[g*4+3]);
                *(float4*)&out[o1] = make_float4(hi[g*4], hi[g*4+1], hi[g*4+2], hi[g*4+3]);
            } else {
                #pragma unroll
                for (int j = 0; j < 4; j++)
                    if (cb + j < NITEMS) { out[o0 + j] = lo[g*4+j]; out[o1 + j] = hi[g*4+j]; }
            }
        }
    }
}

// ================= l2 norm =================
__global__ void k_l2zero() { if (threadIdx.x < 2) g_l2[threadIdx.x] = 0.f; }

__global__ void k_l2reduce(const float* __restrict__ W_lin, const float* __restrict__ b_lin) {
    __shared__ float sh[256];
    int tid = threadIdx.x;
    int stride = gridDim.x * blockDim.x;
    float sw = 0.f;
    for (size_t i = blockIdx.x * blockDim.x + tid; i < (size_t)NITEMS * KL; i += stride) {
        float v = W_lin[i]; sw += v * v;
    }
    float sb = 0.f;
    for (int i = blockIdx.x * blockDim.x + tid; i < NITEMS; i += stride) {
        float v = b_lin[i]; sb += v * v;
    }
    sh[tid] = sw; __syncthreads();
    for (int s = 128; s > 0; s >>= 1) { if (tid < s) sh[tid] += sh[tid + s]; __syncthreads(); }
    if (tid == 0) atomicAdd(&g_l2[0], sh[0]);
    __syncthreads();
    sh[tid] = sb; __syncthreads();
    for (int s = 128; s > 0; s >>= 1) { if (tid < s) sh[tid] += sh[tid + s]; __syncthreads(); }
    if (tid == 0) atomicAdd(&g_l2[1], sh[0]);
}

__global__ void k_l2final(float* __restrict__ out, int has_scalar) {
    if (has_scalar && threadIdx.x == 0)
        out[NPN] = sqrtf(g_l2[0]) + sqrtf(g_l2[1]);
}

// ================= launch =================
extern "C" void kernel_launch(void* const* d_in, const int* in_sizes, int n_in,
                              void* d_out, int out_size) {
    const int*   act   = (const int*)  d_in[0];
    const float* rew   = (const float*)d_in[1];
    const float* stat  = (const float*)d_in[2];
    const float* hx    = (const float*)d_in[3];
    const float* cx    = (const float*)d_in[4];
    const float* emb   = (const float*)d_in[5];
    const float* W_ih  = (const float*)d_in[6];
    const float* W_hh  = (const float*)d_in[7];
    const float* b_ih  = (const float*)d_in[8];
    const float* b_hh  = (const float*)d_in[9];
    const float* W_lin = (const float*)d_in[10];
    const float* b_lin = (const float*)d_in[11];
    float* out = (float*)d_out;

    k_init<<<(BB * HH + 255) / 256, 256>>>(hx, cx);
    k_ars<<<(TT * BB * 32 + 255) / 256, 256>>>(act, rew, stat, emb);
    k_statcopy<<<(TT * BB * 8 + 255) / 256, 256>>>(stat);
    k_xproj<<<dim3(GG / 128, TT * BB / 128), 256>>>(W_ih, b_ih, b_hh);

    for (int t = 0; t < TT; t++)
        k_lstm<<<dim3(HH / 16, BB / 32), 256>>>(W_hh, t, t & 1);

    k_lin<<<dim3((NITEMS + 127) / 128, TT * BB / 128), 256>>>(W_lin, b_lin, out);

    k_l2zero<<<1, 32>>>();
    k_l2reduce<<<512, 256>>>(W_lin, b_lin);
    k_l2final<<<1, 32>>>(out, out_size > NPN ? 1 : 0);
}

// round 9
// speedup vs baseline: 1.6756x; 1.5154x over previous
#include <cuda_runtime.h>
#include <cuda_bf16.h>
#include <math.h>
#include <stdint.h>

#define TT 100
#define BB 128
#define HH 512
#define GG 2048            // 4*H
#define NIN 128            // rnn input dim
#define NITEMS 10000
#define KL 544             // H + SDIM
#define NPN 128000000      // TT*BB*NITEMS
#define KP 576             // K padded (row stride for split buffers)
#define NP 10112           // items padded to 79*128

// HMMA GEMM config for final linear
#define LIN_STAGES 51      // 3 passes * 544/32
#define PASS_STEPS 17      // 544/32
#define LDS_PAD 40         // 32 data + 8 pad bf16 per smem row

typedef unsigned long long ull;

// ---------------- static device scratch (no runtime allocation) ----------------
__device__ float g_ars[TT * BB * NIN];
__device__ float g_xproj[TT * BB * GG];
__device__ float g_linin[TT * BB * KL];
__device__ float g_h[2][BB * HH];
__device__ float g_c[BB * HH];
__device__ float g_l2[2];
__device__ __nv_bfloat16 g_Ah[(size_t)TT * BB * KP];
__device__ __nv_bfloat16 g_Al[(size_t)TT * BB * KP];
__device__ __nv_bfloat16 g_Bh[(size_t)NP * KP];
__device__ __nv_bfloat16 g_Bl[(size_t)NP * KP];

// ---------------- f32x2 helpers ----------------
__device__ __forceinline__ ull pack2(float x, float y) {
    ull v; asm("mov.b64 %0,{%1,%2};" : "=l"(v) : "f"(x), "f"(y)); return v;
}
__device__ __forceinline__ float2 unpack2(ull v) {
    float2 f; asm("mov.b64 {%0,%1},%2;" : "=f"(f.x), "=f"(f.y) : "l"(v)); return f;
}
__device__ __forceinline__ void fma2(ull &c, ull a, ull b) {
    asm("fma.rn.f32x2 %0,%1,%2,%3;" : "=l"(c) : "l"(a), "l"(b), "l"(c));
}
__device__ __forceinline__ float sigf(float x) { return 1.0f / (1.0f + expf(-x)); }

__device__ __forceinline__ uint32_t smem_u32(const void* p) {
    uint32_t a;
    asm("{ .reg .u64 t; cvta.to.shared.u64 t, %1; cvt.u32.u64 %0, t; }" : "=r"(a) : "l"(p));
    return a;
}

// ---------------- cp.async / ldmatrix / mma (baseline sm_80 PTX) ----------------
#define CP_ASYNC16(sdst, gsrc) \
    asm volatile("cp.async.cg.shared.global [%0], [%1], 16;" :: "r"(sdst), "l"(gsrc))
#define CP_COMMIT() asm volatile("cp.async.commit_group;" ::: "memory")
#define CP_WAIT(n)  asm volatile("cp.async.wait_group %0;" :: "n"(n) : "memory")

#define LDSM_X4(r0, r1, r2, r3, addr) \
    asm volatile("ldmatrix.sync.aligned.m8n8.x4.shared.b16 {%0,%1,%2,%3}, [%4];" \
        : "=r"(r0), "=r"(r1), "=r"(r2), "=r"(r3) : "r"(addr))
#define LDSM_X2(r0, r1, addr) \
    asm volatile("ldmatrix.sync.aligned.m8n8.x2.shared.b16 {%0,%1}, [%2];" \
        : "=r"(r0), "=r"(r1) : "r"(addr))

#define MMA16816(c0, c1, c2, c3, a0, a1, a2, a3, b0, b1) \
    asm volatile("mma.sync.aligned.m16n8k16.row.col.f32.bf16.bf16.f32 " \
        "{%0,%1,%2,%3}, {%4,%5,%6,%7}, {%8,%9}, {%0,%1,%2,%3};" \
        : "+f"(c0), "+f"(c1), "+f"(c2), "+f"(c3) \
        : "r"(a0), "r"(a1), "r"(a2), "r"(a3), "r"(b0), "r"(b1))

// ================= init =================
__global__ void k_init(const float* __restrict__ hx, const float* __restrict__ cx) {
    int i = blockIdx.x * blockDim.x + threadIdx.x;
    if (i < BB * HH) { g_h[0][i] = hx[i]; g_c[i] = cx[i]; }
}

// ================= build ars =================
__global__ void k_ars(const int* __restrict__ act, const float* __restrict__ rew,
                      const float* __restrict__ stat, const float* __restrict__ emb) {
    int idx = blockIdx.x * blockDim.x + threadIdx.x;
    if (idx >= TT * BB * 32) return;
    int tb = idx >> 5;
    int k = (idx & 31) * 4;
    float4 v;
    if (k < 64) {
        v = *(const float4*)&emb[(size_t)act[tb] * 64 + k];
    } else if (k < 96) {
        float r = rew[tb];
        int ri = (int)floorf((32.0f * (2.0f - r)) / 4.0f);
        int kb = k - 64;
        v.x = (ri == kb    ) ? 1.f : 0.f;
        v.y = (ri == kb + 1) ? 1.f : 0.f;
        v.z = (ri == kb + 2) ? 1.f : 0.f;
        v.w = (ri == kb + 3) ? 1.f : 0.f;
    } else {
        v = *(const float4*)&stat[(size_t)tb * 32 + (k - 96)];
    }
    *(float4*)&g_ars[(size_t)tb * NIN + k] = v;
}

// ================= statcopy =================
__global__ void k_statcopy(const float* __restrict__ stat) {
    int i4 = blockIdx.x * blockDim.x + threadIdx.x;
    if (i4 < TT * BB * 8) {
        int tb = i4 >> 3, s4 = i4 & 7;
        float4 v = *(const float4*)&stat[(size_t)tb * 32 + s4 * 4];
        *(float4*)&g_linin[(size_t)tb * KL + HH + s4 * 4] = v;
    }
}

// ================= x_proj (unchanged, known passing) ==================
__global__ __launch_bounds__(256, 2) void k_xproj(
    const float* __restrict__ W_ih, const float* __restrict__ b_ih,
    const float* __restrict__ b_hh)
{
    __shared__ __align__(16) float A_s[8][132];
    __shared__ __align__(16) float B2_s[8][264];
    const int tid = threadIdx.x;
    const int g0  = blockIdx.x * 128;
    const int tb0 = blockIdx.y * 128;
    const int tx = tid & 15;
    const int ty = tid >> 4;
    const int mf = tid >> 1;
    const int kf = (tid & 1) * 4;

    ull acc[4][8];
    #pragma unroll
    for (int i = 0; i < 4; i++)
        #pragma unroll
        for (int j = 0; j < 8; j++) acc[i][j] = 0ull;

    float4 rA = *(const float4*)&g_ars[(size_t)(tb0 + mf) * NIN + kf];
    float4 rB = *(const float4*)&W_ih[(size_t)(g0 + mf) * NIN + kf];

    for (int kt = 0; kt < NIN / 8; kt++) {
        A_s[kf + 0][mf] = rA.x; A_s[kf + 1][mf] = rA.y;
        A_s[kf + 2][mf] = rA.z; A_s[kf + 3][mf] = rA.w;
        *(ull*)&B2_s[kf + 0][2 * mf] = pack2(rB.x, rB.x);
        *(ull*)&B2_s[kf + 1][2 * mf] = pack2(rB.y, rB.y);
        *(ull*)&B2_s[kf + 2][2 * mf] = pack2(rB.z, rB.z);
        *(ull*)&B2_s[kf + 3][2 * mf] = pack2(rB.w, rB.w);
        __syncthreads();
        if (kt + 1 < NIN / 8) {
            int k0n = (kt + 1) * 8;
            rA = *(const float4*)&g_ars[(size_t)(tb0 + mf) * NIN + k0n + kf];
            rB = *(const float4*)&W_ih[(size_t)(g0 + mf) * NIN + k0n + kf];
        }
        #pragma unroll
        for (int k = 0; k < 8; k++) {
            ulonglong2 a01 = *(const ulonglong2*)&A_s[k][tx * 8];
            ulonglong2 a23 = *(const ulonglong2*)&A_s[k][tx * 8 + 4];
            ull a[4] = {a01.x, a01.y, a23.x, a23.y};
            #pragma unroll
            for (int jh = 0; jh < 2; jh++) {
                ulonglong2 b01 = *(const ulonglong2*)&B2_s[k][ty * 16 + jh * 8];
                ulonglong2 b23 = *(const ulonglong2*)&B2_s[k][ty * 16 + jh * 8 + 4];
                ull b[4] = {b01.x, b01.y, b23.x, b23.y};
                #pragma unroll
                for (int i = 0; i < 4; i++)
                    #pragma unroll
                    for (int j = 0; j < 4; j++)
                        fma2(acc[i][jh * 4 + j], a[i], b[j]);
            }
        }
        __syncthreads();
    }
    float bs[8];
    #pragma unroll
    for (int j = 0; j < 8; j++) {
        int g = g0 + ty * 8 + j;
        bs[j] = b_ih[g] + b_hh[g];
    }
    #pragma unroll
    for (int rp = 0; rp < 4; rp++) {
        float lo[8], hi[8];
        #pragma unroll
        for (int j = 0; j < 8; j++) {
            float2 c = unpack2(acc[rp][j]);
            lo[j] = c.x + bs[j]; hi[j] = c.y + bs[j];
        }
        int row = tb0 + tx * 8 + rp * 2;
        size_t o0 = (size_t)row * GG + g0 + ty * 8;
        *(float4*)&g_xproj[o0]          = make_float4(lo[0], lo[1], lo[2], lo[3]);
        *(float4*)&g_xproj[o0 + 4]      = make_float4(lo[4], lo[5], lo[6], lo[7]);
        *(float4*)&g_xproj[o0 + GG]     = make_float4(hi[0], hi[1], hi[2], hi[3]);
        *(float4*)&g_xproj[o0 + GG + 4] = make_float4(hi[4], hi[5], hi[6], hi[7]);
    }
}

// ================= LSTM step (unchanged, known passing) =================
__global__ __launch_bounds__(256) void k_lstm(const float* __restrict__ W_hh, int t, int src)
{
    __shared__ __align__(16) float h_s[32][34];
    __shared__ __align__(16) float w2_s[32][132];
    __shared__ float gs[32][65];

    const int tid = threadIdx.x;
    const int m0 = blockIdx.x * 16;
    const int r0 = blockIdx.y * 32;
    const int tx = tid & 7;
    const int ty = tid >> 3;
    const float* __restrict__ hsrc = g_h[src];
    const int dst = src ^ 1;

    ull acc[2][2];
    acc[0][0] = acc[0][1] = acc[1][0] = acc[1][1] = 0ull;

    for (int kk0 = 0; kk0 < HH; kk0 += 32) {
        __syncthreads();
        {
            int r = tid >> 3, k4 = tid & 7;
            float4 v = *(const float4*)&hsrc[(size_t)(r0 + r) * HH + kk0 + k4 * 4];
            h_s[k4 * 4 + 0][r] = v.x; h_s[k4 * 4 + 1][r] = v.y;
            h_s[k4 * 4 + 2][r] = v.z; h_s[k4 * 4 + 3][r] = v.w;
        }
        #pragma unroll
        for (int i = 0; i < 2; i++) {
            int idx = tid + i * 256;
            int c = idx >> 3, k4 = idx & 7;
            int gcol = (c >> 4) * HH + m0 + (c & 15);
            float4 v = *(const float4*)&W_hh[(size_t)gcol * HH + kk0 + k4 * 4];
            *(ull*)&w2_s[k4 * 4 + 0][2 * c] = pack2(v.x, v.x);
            *(ull*)&w2_s[k4 * 4 + 1][2 * c] = pack2(v.y, v.y);
            *(ull*)&w2_s[k4 * 4 + 2][2 * c] = pack2(v.z, v.z);
            *(ull*)&w2_s[k4 * 4 + 3][2 * c] = pack2(v.w, v.w);
        }
        __syncthreads();
        #pragma unroll
        for (int k = 0; k < 32; k++) {
            ull a0 = *(const ull*)&h_s[k][tx * 4];
            ull a1 = *(const ull*)&h_s[k][tx * 4 + 2];
            ulonglong2 b = *(const ulonglong2*)&w2_s[k][ty * 4];
            fma2(acc[0][0], a0, b.x); fma2(acc[0][1], a0, b.y);
            fma2(acc[1][0], a1, b.x); fma2(acc[1][1], a1, b.y);
        }
    }
    __syncthreads();
    #pragma unroll
    for (int pi = 0; pi < 2; pi++) {
        float2 v0 = unpack2(acc[pi][0]);
        float2 v1 = unpack2(acc[pi][1]);
        int r = tx * 4 + pi * 2;
        int c0 = ty * 2, c1 = ty * 2 + 1;
        int gcol0 = (c0 >> 4) * HH + m0 + (c0 & 15);
        int gcol1 = (c1 >> 4) * HH + m0 + (c1 & 15);
        size_t base = ((size_t)t * BB + r0 + r) * GG;
        gs[r][c0]     = v0.x + g_xproj[base + gcol0];
        gs[r + 1][c0] = v0.y + g_xproj[base + GG + gcol0];
        gs[r][c1]     = v1.x + g_xproj[base + gcol1];
        gs[r + 1][c1] = v1.y + g_xproj[base + GG + gcol1];
    }
    __syncthreads();
    #pragma unroll
    for (int e = 0; e < 2; e++) {
        int p = tid * 2 + e;
        int r = p >> 4, mi = p & 15;
        float gi = gs[r][mi];
        float gf = gs[r][16 + mi];
        float gg = gs[r][32 + mi];
        float go = gs[r][48 + mi];
        int b = r0 + r, m = m0 + mi;
        int ci = b * HH + m;
        float cn = sigf(gf) * g_c[ci] + sigf(gi) * tanhf(gg);
        float h = sigf(go) * tanhf(cn);
        g_c[ci] = cn;
        g_h[dst][ci] = h;
        g_linin[((size_t)t * BB + b) * KL + m] = h;
    }
}

// ================= bf16 hi/lo split prep =================
__global__ void k_splitB(const float* __restrict__ W) {
    int idx = blockIdx.x * blockDim.x + threadIdx.x;   // over NP * (KP/4)
    if (idx >= NP * (KP / 4)) return;
    int row = idx / (KP / 4);
    int c4 = (idx % (KP / 4)) * 4;
    float v[4] = {0.f, 0.f, 0.f, 0.f};
    if (row < NITEMS) {
        #pragma unroll
        for (int j = 0; j < 4; j++) {
            int c = c4 + j;
            if (c < KL) v[j] = W[(size_t)row * KL + c];
        }
    }
    __nv_bfloat16 h[4], l[4];
    #pragma unroll
    for (int j = 0; j < 4; j++) {
        h[j] = __float2bfloat16(v[j]);
        l[j] = __float2bfloat16(v[j] - __bfloat162float(h[j]));
    }
    size_t o = (size_t)row * KP + c4;
    *(__nv_bfloat162*)&g_Bh[o]     = __nv_bfloat162(h[0], h[1]);
    *(__nv_bfloat162*)&g_Bh[o + 2] = __nv_bfloat162(h[2], h[3]);
    *(__nv_bfloat162*)&g_Bl[o]     = __nv_bfloat162(l[0], l[1]);
    *(__nv_bfloat162*)&g_Bl[o + 2] = __nv_bfloat162(l[2], l[3]);
}

__global__ void k_splitA() {
    int idx = blockIdx.x * blockDim.x + threadIdx.x;   // over TT*BB * (KP/4)
    if (idx >= TT * BB * (KP / 4)) return;
    int row = idx / (KP / 4);
    int c4 = (idx % (KP / 4)) * 4;
    float v[4] = {0.f, 0.f, 0.f, 0.f};
    #pragma unroll
    for (int j = 0; j < 4; j++) {
        int c = c4 + j;
        if (c < KL) v[j] = g_linin[(size_t)row * KL + c];
    }
    __nv_bfloat16 h[4], l[4];
    #pragma unroll
    for (int j = 0; j < 4; j++) {
        h[j] = __float2bfloat16(v[j]);
        l[j] = __float2bfloat16(v[j] - __bfloat162float(h[j]));
    }
    size_t o = (size_t)row * KP + c4;
    *(__nv_bfloat162*)&g_Ah[o]     = __nv_bfloat162(h[0], h[1]);
    *(__nv_bfloat162*)&g_Ah[o + 2] = __nv_bfloat162(h[2], h[3]);
    *(__nv_bfloat162*)&g_Al[o]     = __nv_bfloat162(l[0], l[1]);
    *(__nv_bfloat162*)&g_Al[o + 2] = __nv_bfloat162(l[2], l[3]);
}

// ================= final linear via mma.sync bf16 (split, 3 logical passes) ======
// CTA tile 128x128, 8 warps (2x4), warp tile 64x32, BK=32, cp.async double buffer.
// K_eff = 1632: stage s -> pass p=s/17 (Ah*Bh, Al*Bh, Ah*Bl), kk=(s%17)*32.
__global__ __launch_bounds__(256) void k_lin_hmma(const float* __restrict__ b_lin,
                                                  float* __restrict__ out)
{
    __shared__ __align__(16) __nv_bfloat16 As[2][128 * LDS_PAD];
    __shared__ __align__(16) __nv_bfloat16 Bs[2][128 * LDS_PAD];
    __shared__ float bias_s[128];

    const int tid = threadIdx.x;
    const int lane = tid & 31;
    const int wid = tid >> 5;
    const int warp_m = wid & 1;        // 0..1 -> m offset *64
    const int warp_n = wid >> 1;       // 0..3 -> n offset *32
    const int tb0 = blockIdx.x * 128;  // row block (fast dim -> B reuse in L2)
    const int v0  = blockIdx.y * 128;  // item block

    if (tid < 128) {
        int v = v0 + tid;
        bias_s[tid] = (v < NITEMS) ? b_lin[v] : 0.f;
    }

    const uint32_t aB0 = smem_u32(As);
    const uint32_t bB0 = smem_u32(Bs);

    float c[4][4][4];
    #pragma unroll
    for (int mi = 0; mi < 4; mi++)
        #pragma unroll
        for (int ni = 0; ni < 4; ni++)
            #pragma unroll
            for (int e = 0; e < 4; e++) c[mi][ni][e] = 0.f;

    // per-thread load assignment: 512 16B chunks per tile, 2 per thread per tile
    const int lr0 = tid >> 1;                 // not used directly; see below
    (void)lr0;

    // loader: stage s into buffer d
    auto load_stage = [&](int s, int d) {
        int p = s / PASS_STEPS;
        int kk = (s % PASS_STEPS) * 32;
        const __nv_bfloat16* Asrc = ((p == 1) ? g_Al : g_Ah) + (size_t)tb0 * KP + kk;
        const __nv_bfloat16* Bsrc = ((p == 2) ? g_Bl : g_Bh) + (size_t)v0  * KP + kk;
        uint32_t aB = aB0 + d * (128 * LDS_PAD * 2);
        uint32_t bB = bB0 + d * (128 * LDS_PAD * 2);
        #pragma unroll
        for (int it = 0; it < 2; it++) {
            int idx = tid + it * 256;          // 0..511
            int r = idx >> 2, c16 = idx & 3;
            CP_ASYNC16(aB + (r * LDS_PAD + c16 * 8) * 2,
                       (const char*)(Asrc + (size_t)r * KP + c16 * 8));
            CP_ASYNC16(bB + (r * LDS_PAD + c16 * 8) * 2,
                       (const char*)(Bsrc + (size_t)r * KP + c16 * 8));
        }
        CP_COMMIT();
    };

    load_stage(0, 0);

    for (int s = 0; s < LIN_STAGES; s++) {
        int d = s & 1;
        if (s + 1 < LIN_STAGES) {
            load_stage(s + 1, (s + 1) & 1);
            CP_WAIT(1);
        } else {
            CP_WAIT(0);
        }
        __syncthreads();

        uint32_t aB = aB0 + d * (128 * LDS_PAD * 2);
        uint32_t bB = bB0 + d * (128 * LDS_PAD * 2);
        #pragma unroll
        for (int ks = 0; ks < 2; ks++) {
            uint32_t a[4][4], b[4][2];
            #pragma unroll
            for (int mi = 0; mi < 4; mi++) {
                int row = warp_m * 64 + mi * 16 + (lane & 15);
                int col = ks * 16 + (lane >> 4) * 8;
                uint32_t ad = aB + (row * LDS_PAD + col) * 2;
                LDSM_X4(a[mi][0], a[mi][1], a[mi][2], a[mi][3], ad);
            }
            #pragma unroll
            for (int ni = 0; ni < 4; ni++) {
                int row = warp_n * 32 + ni * 8 + (lane & 7);
                int col = ks * 16 + ((lane >> 3) & 1) * 8;
                uint32_t bd = bB + (row * LDS_PAD + col) * 2;
                LDSM_X2(b[ni][0], b[ni][1], bd);
            }
            #pragma unroll
            for (int mi = 0; mi < 4; mi++)
                #pragma unroll
                for (int ni = 0; ni < 4; ni++)
                    MMA16816(c[mi][ni][0], c[mi][ni][1], c[mi][ni][2], c[mi][ni][3],
                             a[mi][0], a[mi][1], a[mi][2], a[mi][3],
                             b[ni][0], b[ni][1]);
        }
        __syncthreads();
    }

    // epilogue: direct float2 stores with bias; n even, NITEMS even
    #pragma unroll
    for (int mi = 0; mi < 4; mi++) {
        int m = tb0 + warp_m * 64 + mi * 16 + (lane >> 2);
        #pragma unroll
        for (int ni = 0; ni < 4; ni++) {
            int nl = warp_n * 32 + ni * 8 + (lane & 3) * 2;
            int n = v0 + nl;
            if (n < NITEMS) {
                float b0v = bias_s[nl], b1v = bias_s[nl + 1];
                *(float2*)&out[(size_t)m * NITEMS + n] =
                    make_float2(c[mi][ni][0] + b0v, c[mi][ni][1] + b1v);
                *(float2*)&out[(size_t)(m + 8) * NITEMS + n] =
                    make_float2(c[mi][ni][2] + b0v, c[mi][ni][3] + b1v);
            }
        }
    }
}

// ================= l2 norm =================
__global__ void k_l2zero() { if (threadIdx.x < 2) g_l2[threadIdx.x] = 0.f; }

__global__ void k_l2reduce(const float* __restrict__ W_lin, const float* __restrict__ b_lin) {
    __shared__ float sh[256];
    int tid = threadIdx.x;
    int stride = gridDim.x * blockDim.x;
    float sw = 0.f;
    for (size_t i = blockIdx.x * blockDim.x + tid; i < (size_t)NITEMS * KL; i += stride) {
        float v = W_lin[i]; sw += v * v;
    }
    float sb = 0.f;
    for (int i = blockIdx.x * blockDim.x + tid; i < NITEMS; i += stride) {
        float v = b_lin[i]; sb += v * v;
    }
    sh[tid] = sw; __syncthreads();
    for (int s = 128; s > 0; s >>= 1) { if (tid < s) sh[tid] += sh[tid + s]; __syncthreads(); }
    if (tid == 0) atomicAdd(&g_l2[0], sh[0]);
    __syncthreads();
    sh[tid] = sb; __syncthreads();
    for (int s = 128; s > 0; s >>= 1) { if (tid < s) sh[tid] += sh[tid + s]; __syncthreads(); }
    if (tid == 0) atomicAdd(&g_l2[1], sh[0]);
}

__global__ void k_l2final(float* __restrict__ out, int has_scalar) {
    if (has_scalar && threadIdx.x == 0)
        out[NPN] = sqrtf(g_l2[0]) + sqrtf(g_l2[1]);
}

// ================= launch =================
extern "C" void kernel_launch(void* const* d_in, const int* in_sizes, int n_in,
                              void* d_out, int out_size) {
    const int*   act   = (const int*)  d_in[0];
    const float* rew   = (const float*)d_in[1];
    const float* stat  = (const float*)d_in[2];
    const float* hx    = (const float*)d_in[3];
    const float* cx    = (const float*)d_in[4];
    const float* emb   = (const float*)d_in[5];
    const float* W_ih  = (const float*)d_in[6];
    const float* W_hh  = (const float*)d_in[7];
    const float* b_ih  = (const float*)d_in[8];
    const float* b_hh  = (const float*)d_in[9];
    const float* W_lin = (const float*)d_in[10];
    const float* b_lin = (const float*)d_in[11];
    float* out = (float*)d_out;

    k_init<<<(BB * HH + 255) / 256, 256>>>(hx, cx);
    k_ars<<<(TT * BB * 32 + 255) / 256, 256>>>(act, rew, stat, emb);
    k_statcopy<<<(TT * BB * 8 + 255) / 256, 256>>>(stat);
    k_xproj<<<dim3(GG / 128, TT * BB / 128), 256>>>(W_ih, b_ih, b_hh);
    k_splitB<<<(NP * (KP / 4) + 255) / 256, 256>>>(W_lin);

    for (int t = 0; t < TT; t++)
        k_lstm<<<dim3(HH / 16, BB / 32), 256>>>(W_hh, t, t & 1);

    k_splitA<<<(TT * BB * (KP / 4) + 255) / 256, 256>>>();

    // grid.x = row blocks (fast) so consecutive CTAs share the same B column block
    k_lin_hmma<<<dim3(TT * BB / 128, NP / 128), 256>>>(b_lin, out);

    k_l2zero<<<1, 32>>>();
    k_l2reduce<<<512, 256>>>(W_lin, b_lin);
    k_l2final<<<1, 32>>>(out, out_size > NPN ? 1 : 0);
}

// round 11
// speedup vs baseline: 1.8180x; 1.0850x over previous
#include <cuda_runtime.h>
#include <cuda_bf16.h>
#include <math.h>
#include <stdint.h>

#define TT 100
#define BB 128
#define HH 512
#define GG 2048            // 4*H
#define NIN 128            // rnn input dim
#define NITEMS 10000
#define KL 544             // H + SDIM
#define NPN 128000000      // TT*BB*NITEMS
#define KP 576             // K padded (row stride for split buffers)
#define NP 10112           // items padded to 79*128

// HMMA GEMM config for final linear
#define LIN_STAGES 51      // 3 passes * 544/32
#define PASS_STEPS 17      // 544/32
#define LDS_PAD 40         // 32 data + 8 pad bf16 per smem row

// persistent LSTM config
#define LSTM_CTAS 128
#define HS_STRIDE 66       // h_s k-row stride: EVEN (f32x2 pair alignment) + bank-spread

typedef unsigned long long ull;

// ---------------- static device scratch (no runtime allocation) ----------------
__device__ float g_ars[TT * BB * NIN];
__device__ float g_xproj[TT * BB * GG];
__device__ float g_h[2][BB * HH];
__device__ float g_l2[2];
__device__ unsigned g_barrier;
__device__ __nv_bfloat16 g_Ah[(size_t)TT * BB * KP];
__device__ __nv_bfloat16 g_Al[(size_t)TT * BB * KP];
__device__ __nv_bfloat16 g_Bh[(size_t)NP * KP];
__device__ __nv_bfloat16 g_Bl[(size_t)NP * KP];

// ---------------- f32x2 helpers ----------------
__device__ __forceinline__ ull pack2(float x, float y) {
    ull v; asm("mov.b64 %0,{%1,%2};" : "=l"(v) : "f"(x), "f"(y)); return v;
}
__device__ __forceinline__ float2 unpack2(ull v) {
    float2 f; asm("mov.b64 {%0,%1},%2;" : "=f"(f.x), "=f"(f.y) : "l"(v)); return f;
}
__device__ __forceinline__ void fma2(ull &c, ull a, ull b) {
    asm("fma.rn.f32x2 %0,%1,%2,%3;" : "=l"(c) : "l"(a), "l"(b), "l"(c));
}
__device__ __forceinline__ float sigf(float x) { return 1.0f / (1.0f + expf(-x)); }

__device__ __forceinline__ uint32_t smem_u32(const void* p) {
    uint32_t a;
    asm("{ .reg .u64 t; cvta.to.shared.u64 t, %1; cvt.u32.u64 %0, t; }" : "=r"(a) : "l"(p));
    return a;
}

// ---------------- cp.async / ldmatrix / mma (baseline sm_80 PTX) ----------------
#define CP_ASYNC16(sdst, gsrc) \
    asm volatile("cp.async.cg.shared.global [%0], [%1], 16;" :: "r"(sdst), "l"(gsrc))
#define CP_COMMIT() asm volatile("cp.async.commit_group;" ::: "memory")
#define CP_WAIT(n)  asm volatile("cp.async.wait_group %0;" :: "n"(n) : "memory")

#define LDSM_X4(r0, r1, r2, r3, addr) \
    asm volatile("ldmatrix.sync.aligned.m8n8.x4.shared.b16 {%0,%1,%2,%3}, [%4];" \
        : "=r"(r0), "=r"(r1), "=r"(r2), "=r"(r3) : "r"(addr))
#define LDSM_X2(r0, r1, addr) \
    asm volatile("ldmatrix.sync.aligned.m8n8.x2.shared.b16 {%0,%1}, [%2];" \
        : "=r"(r0), "=r"(r1) : "r"(addr))

#define MMA16816(c0, c1, c2, c3, a0, a1, a2, a3, b0, b1) \
    asm volatile("mma.sync.aligned.m16n8k16.row.col.f32.bf16.bf16.f32 " \
        "{%0,%1,%2,%3}, {%4,%5,%6,%7}, {%8,%9}, {%0,%1,%2,%3};" \
        : "+f"(c0), "+f"(c1), "+f"(c2), "+f"(c3) \
        : "r"(a0), "r"(a1), "r"(a2), "r"(a3), "r"(b0), "r"(b1))

// ================= init (also resets grid barrier each replay) =================
__global__ void k_init(const float* __restrict__ hx) {
    int i = blockIdx.x * blockDim.x + threadIdx.x;
    if (i < BB * HH) g_h[0][i] = hx[i];
    if (i == 0) g_barrier = 0u;
}

// ================= build ars =================
__global__ void k_ars(const int* __restrict__ act, const float* __restrict__ rew,
                      const float* __restrict__ stat, const float* __restrict__ emb) {
    int idx = blockIdx.x * blockDim.x + threadIdx.x;
    if (idx >= TT * BB * 32) return;
    int tb = idx >> 5;
    int k = (idx & 31) * 4;
    float4 v;
    if (k < 64) {
        v = *(const float4*)&emb[(size_t)act[tb] * 64 + k];
    } else if (k < 96) {
        float r = rew[tb];
        int ri = (int)floorf((32.0f * (2.0f - r)) / 4.0f);
        int kb = k - 64;
        v.x = (ri == kb    ) ? 1.f : 0.f;
        v.y = (ri == kb + 1) ? 1.f : 0.f;
        v.z = (ri == kb + 2) ? 1.f : 0.f;
        v.w = (ri == kb + 3) ? 1.f : 0.f;
    } else {
        v = *(const float4*)&stat[(size_t)tb * 32 + (k - 96)];
    }
    *(float4*)&g_ars[(size_t)tb * NIN + k] = v;
}

// ================= statsplit: A cols 512..543 = split-bf16(stat) =================
__global__ void k_statsplit(const float* __restrict__ stat) {
    int idx = blockIdx.x * blockDim.x + threadIdx.x;   // over 12800*32
    if (idx >= TT * BB * 32) return;
    int tb = idx >> 5, s = idx & 31;
    float v = stat[(size_t)tb * 32 + s];
    __nv_bfloat16 hh = __float2bfloat16(v);
    __nv_bfloat16 hl = __float2bfloat16(v - __bfloat162float(hh));
    size_t o = (size_t)tb * KP + HH + s;
    g_Ah[o] = hh;
    g_Al[o] = hl;
}

// ================= x_proj (unchanged, known passing) ==================
__global__ __launch_bounds__(256, 2) void k_xproj(
    const float* __restrict__ W_ih, const float* __restrict__ b_ih,
    const float* __restrict__ b_hh)
{
    __shared__ __align__(16) float A_s[8][132];
    __shared__ __align__(16) float B2_s[8][264];
    const int tid = threadIdx.x;
    const int g0  = blockIdx.x * 128;
    const int tb0 = blockIdx.y * 128;
    const int tx = tid & 15;
    const int ty = tid >> 4;
    const int mf = tid >> 1;
    const int kf = (tid & 1) * 4;

    ull acc[4][8];
    #pragma unroll
    for (int i = 0; i < 4; i++)
        #pragma unroll
        for (int j = 0; j < 8; j++) acc[i][j] = 0ull;

    float4 rA = *(const float4*)&g_ars[(size_t)(tb0 + mf) * NIN + kf];
    float4 rB = *(const float4*)&W_ih[(size_t)(g0 + mf) * NIN + kf];

    for (int kt = 0; kt < NIN / 8; kt++) {
        A_s[kf + 0][mf] = rA.x; A_s[kf + 1][mf] = rA.y;
        A_s[kf + 2][mf] = rA.z; A_s[kf + 3][mf] = rA.w;
        *(ull*)&B2_s[kf + 0][2 * mf] = pack2(rB.x, rB.x);
        *(ull*)&B2_s[kf + 1][2 * mf] = pack2(rB.y, rB.y);
        *(ull*)&B2_s[kf + 2][2 * mf] = pack2(rB.z, rB.z);
        *(ull*)&B2_s[kf + 3][2 * mf] = pack2(rB.w, rB.w);
        __syncthreads();
        if (kt + 1 < NIN / 8) {
            int k0n = (kt + 1) * 8;
            rA = *(const float4*)&g_ars[(size_t)(tb0 + mf) * NIN + k0n + kf];
            rB = *(const float4*)&W_ih[(size_t)(g0 + mf) * NIN + k0n + kf];
        }
        #pragma unroll
        for (int k = 0; k < 8; k++) {
            ulonglong2 a01 = *(const ulonglong2*)&A_s[k][tx * 8];
            ulonglong2 a23 = *(const ulonglong2*)&A_s[k][tx * 8 + 4];
            ull a[4] = {a01.x, a01.y, a23.x, a23.y};
            #pragma unroll
            for (int jh = 0; jh < 2; jh++) {
                ulonglong2 b01 = *(const ulonglong2*)&B2_s[k][ty * 16 + jh * 8];
                ulonglong2 b23 = *(const ulonglong2*)&B2_s[k][ty * 16 + jh * 8 + 4];
                ull b[4] = {b01.x, b01.y, b23.x, b23.y};
                #pragma unroll
                for (int i = 0; i < 4; i++)
                    #pragma unroll
                    for (int j = 0; j < 4; j++)
                        fma2(acc[i][jh * 4 + j], a[i], b[j]);
            }
        }
        __syncthreads();
    }
    float bs[8];
    #pragma unroll
    for (int j = 0; j < 8; j++) {
        int g = g0 + ty * 8 + j;
        bs[j] = b_ih[g] + b_hh[g];
    }
    #pragma unroll
    for (int rp = 0; rp < 4; rp++) {
        float lo[8], hi[8];
        #pragma unroll
        for (int j = 0; j < 8; j++) {
            float2 c = unpack2(acc[rp][j]);
            lo[j] = c.x + bs[j]; hi[j] = c.y + bs[j];
        }
        int row = tb0 + tx * 8 + rp * 2;
        size_t o0 = (size_t)row * GG + g0 + ty * 8;
        *(float4*)&g_xproj[o0]          = make_float4(lo[0], lo[1], lo[2], lo[3]);
        *(float4*)&g_xproj[o0 + 4]      = make_float4(lo[4], lo[5], lo[6], lo[7]);
        *(float4*)&g_xproj[o0 + GG]     = make_float4(hi[0], hi[1], hi[2], hi[3]);
        *(float4*)&g_xproj[o0 + GG + 4] = make_float4(hi[4], hi[5], hi[6], hi[7]);
    }
}

// ================= persistent LSTM: all 100 steps in ONE launch =================
// Grid (64,2) = 128 CTAs: bx -> 8 h-units (m0 = bx*8, 32 gate cols over 4 gates),
// by -> 64 batch rows (r0 = by*64). Each CTA caches its W_hh slice once, f32x2-dup,
// in SMEM (128KB). Cell state lives in registers. Grid barrier between steps.
// Dyn smem: Wd float[512*64] | h_s float[32*HS_STRIDE] | gs float[64*33]
#define LP_WD_SZ   (512 * 64)
#define LP_HS_OFF  LP_WD_SZ
#define LP_HS_SZ   (32 * HS_STRIDE)
#define LP_GS_OFF  (LP_HS_OFF + LP_HS_SZ + 2)
#define LP_SM_FLOATS (LP_GS_OFF + 64 * 33 + 4)

__global__ __launch_bounds__(256) void k_lstm_persist(
    const float* __restrict__ W_hh, const float* __restrict__ cx)
{
    extern __shared__ __align__(16) float smf[];
    float* Wd  = smf;               // [k 0..511][32 cols dup'd -> 64 floats]
    float* h_s = smf + LP_HS_OFF;   // [k 0..31][r 0..63], stride HS_STRIDE (even!)
    float* gs  = smf + LP_GS_OFF;   // [r 0..63][c 0..31], stride 33

    const int tid = threadIdx.x;
    const int m0 = blockIdx.x * 8;     // h-unit base
    const int r0 = blockIdx.y * 64;    // batch row base
    const int tx = tid & 15;           // row groups: pair0 = 2tx..2tx+1, pair1 = 32+2tx..
    const int ty = tid >> 4;           // col pair: 2ty, 2ty+1 (of 32)

    // ---- one-time: cache W slice, duplicated for f32x2 ----
    #pragma unroll
    for (int it = 0; it < 16; it++) {
        int idx = tid + it * 256;          // 0..4095
        int c = idx >> 7;                  // local col 0..31
        int k4 = idx & 127;                // float4 index along K
        int grow = (c >> 3) * HH + m0 + (c & 7);
        float4 v = *(const float4*)&W_hh[(size_t)grow * HH + k4 * 4];
        *(ull*)&Wd[(size_t)(k4 * 4 + 0) * 64 + 2 * c] = pack2(v.x, v.x);
        *(ull*)&Wd[(size_t)(k4 * 4 + 1) * 64 + 2 * c] = pack2(v.y, v.y);
        *(ull*)&Wd[(size_t)(k4 * 4 + 2) * 64 + 2 * c] = pack2(v.z, v.z);
        *(ull*)&Wd[(size_t)(k4 * 4 + 3) * 64 + 2 * c] = pack2(v.w, v.w);
    }

    // ---- cell state in registers: p = tid*2+e -> r = p>>3, mi = p&7 ----
    float creg[2];
    #pragma unroll
    for (int e = 0; e < 2; e++) {
        int p = tid * 2 + e;
        creg[e] = cx[(size_t)(r0 + (p >> 3)) * HH + m0 + (p & 7)];
    }
    __syncthreads();

    for (int t = 0; t < TT; t++) {
        const float* __restrict__ hsrc = g_h[t & 1];
        float* __restrict__ hdst = g_h[(t + 1) & 1];

        ull acc[2][2];
        acc[0][0] = acc[0][1] = acc[1][0] = acc[1][1] = 0ull;

        for (int kk0 = 0; kk0 < HH; kk0 += 32) {
            __syncthreads();
            // stage h chunk transposed: h_s[k][r], 64 rows x 32 k
            #pragma unroll
            for (int i = 0; i < 2; i++) {
                int idx = tid + i * 256;       // 0..511
                int r = idx >> 3, k4 = idx & 7;
                float4 v = *(const float4*)&hsrc[(size_t)(r0 + r) * HH + kk0 + k4 * 4];
                h_s[(k4 * 4 + 0) * HS_STRIDE + r] = v.x;
                h_s[(k4 * 4 + 1) * HS_STRIDE + r] = v.y;
                h_s[(k4 * 4 + 2) * HS_STRIDE + r] = v.z;
                h_s[(k4 * 4 + 3) * HS_STRIDE + r] = v.w;
            }
            __syncthreads();
            #pragma unroll
            for (int k = 0; k < 32; k++) {
                ull a0 = *(const ull*)&h_s[k * HS_STRIDE + 2 * tx];
                ull a1 = *(const ull*)&h_s[k * HS_STRIDE + 32 + 2 * tx];
                ulonglong2 b = *(const ulonglong2*)&Wd[(size_t)(kk0 + k) * 64 + ty * 4];
                fma2(acc[0][0], a0, b.x); fma2(acc[0][1], a0, b.y);
                fma2(acc[1][0], a1, b.x); fma2(acc[1][1], a1, b.y);
            }
        }

        // gates = acc + xproj, staged to gs
        __syncthreads();
        const int c0 = 2 * ty, c1 = 2 * ty + 1;
        const int gcol0 = (c0 >> 3) * HH + m0 + (c0 & 7);
        const int gcol1 = (c1 >> 3) * HH + m0 + (c1 & 7);
        #pragma unroll
        for (int pi = 0; pi < 2; pi++) {
            float2 v0 = unpack2(acc[pi][0]);
            float2 v1 = unpack2(acc[pi][1]);
            int r = pi * 32 + 2 * tx;
            size_t base = ((size_t)t * BB + r0 + r) * GG;
            gs[r * 33 + c0]       = v0.x + g_xproj[base + gcol0];
            gs[(r + 1) * 33 + c0] = v0.y + g_xproj[base + GG + gcol0];
            gs[r * 33 + c1]       = v1.x + g_xproj[base + gcol1];
            gs[(r + 1) * 33 + c1] = v1.y + g_xproj[base + GG + gcol1];
        }
        __syncthreads();

        // cell update + h writes (fp32 ping-pong + split-bf16 A operand)
        #pragma unroll
        for (int e = 0; e < 2; e++) {
            int p = tid * 2 + e;
            int r = p >> 3, mi = p & 7;
            float gi = gs[r * 33 + mi];
            float gf = gs[r * 33 + 8 + mi];
            float gg = gs[r * 33 + 16 + mi];
            float go = gs[r * 33 + 24 + mi];
            float cn = sigf(gf) * creg[e] + sigf(gi) * tanhf(gg);
            float h = sigf(go) * tanhf(cn);
            creg[e] = cn;
            hdst[(size_t)(r0 + r) * HH + m0 + mi] = h;
            __nv_bfloat16 hh = __float2bfloat16(h);
            __nv_bfloat16 hl = __float2bfloat16(h - __bfloat162float(hh));
            size_t ao = ((size_t)t * BB + r0 + r) * KP + m0 + mi;
            g_Ah[ao] = hh;
            g_Al[ao] = hl;
        }

        // grid barrier (monotonic counter; reset by k_init each replay)
        __syncthreads();
        if (tid == 0) {
            __threadfence();
            atomicAdd(&g_barrier, 1u);
            unsigned tgt = (unsigned)(t + 1) * LSTM_CTAS;
            while (*(volatile unsigned*)&g_barrier < tgt) { }
            __threadfence();
        }
        __syncthreads();
    }
}

// ================= bf16 hi/lo split of W_lin =================
__global__ void k_splitB(const float* __restrict__ W) {
    int idx = blockIdx.x * blockDim.x + threadIdx.x;   // over NP * (KP/4)
    if (idx >= NP * (KP / 4)) return;
    int row = idx / (KP / 4);
    int c4 = (idx % (KP / 4)) * 4;
    float v[4] = {0.f, 0.f, 0.f, 0.f};
    if (row < NITEMS) {
        #pragma unroll
        for (int j = 0; j < 4; j++) {
            int c = c4 + j;
            if (c < KL) v[j] = W[(size_t)row * KL + c];
        }
    }
    __nv_bfloat16 h[4], l[4];
    #pragma unroll
    for (int j = 0; j < 4; j++) {
        h[j] = __float2bfloat16(v[j]);
        l[j] = __float2bfloat16(v[j] - __bfloat162float(h[j]));
    }
    size_t o = (size_t)row * KP + c4;
    *(__nv_bfloat162*)&g_Bh[o]     = __nv_bfloat162(h[0], h[1]);
    *(__nv_bfloat162*)&g_Bh[o + 2] = __nv_bfloat162(h[2], h[3]);
    *(__nv_bfloat162*)&g_Bl[o]     = __nv_bfloat162(l[0], l[1]);
    *(__nv_bfloat162*)&g_Bl[o + 2] = __nv_bfloat162(l[2], l[3]);
}

// ================= final linear via mma.sync bf16 (unchanged, known passing) =====
__global__ __launch_bounds__(256) void k_lin_hmma(const float* __restrict__ b_lin,
                                                  float* __restrict__ out)
{
    __shared__ __align__(16) __nv_bfloat16 As[2][128 * LDS_PAD];
    __shared__ __align__(16) __nv_bfloat16 Bs[2][128 * LDS_PAD];
    __shared__ float bias_s[128];

    const int tid = threadIdx.x;
    const int lane = tid & 31;
    const int wid = tid >> 5;
    const int warp_m = wid & 1;
    const int warp_n = wid >> 1;
    const int tb0 = blockIdx.x * 128;
    const int v0  = blockIdx.y * 128;

    if (tid < 128) {
        int v = v0 + tid;
        bias_s[tid] = (v < NITEMS) ? b_lin[v] : 0.f;
    }

    const uint32_t aB0 = smem_u32(As);
    const uint32_t bB0 = smem_u32(Bs);

    float c[4][4][4];
    #pragma unroll
    for (int mi = 0; mi < 4; mi++)
        #pragma unroll
        for (int ni = 0; ni < 4; ni++)
            #pragma unroll
            for (int e = 0; e < 4; e++) c[mi][ni][e] = 0.f;

    auto load_stage = [&](int s, int d) {
        int p = s / PASS_STEPS;
        int kk = (s % PASS_STEPS) * 32;
        const __nv_bfloat16* Asrc = ((p == 1) ? g_Al : g_Ah) + (size_t)tb0 * KP + kk;
        const __nv_bfloat16* Bsrc = ((p == 2) ? g_Bl : g_Bh) + (size_t)v0  * KP + kk;
        uint32_t aB = aB0 + d * (128 * LDS_PAD * 2);
        uint32_t bB = bB0 + d * (128 * LDS_PAD * 2);
        #pragma unroll
        for (int it = 0; it < 2; it++) {
            int idx = tid + it * 256;
            int r = idx >> 2, c16 = idx & 3;
            CP_ASYNC16(aB + (r * LDS_PAD + c16 * 8) * 2,
                       (const char*)(Asrc + (size_t)r * KP + c16 * 8));
            CP_ASYNC16(bB + (r * LDS_PAD + c16 * 8) * 2,
                       (const char*)(Bsrc + (size_t)r * KP + c16 * 8));
        }
        CP_COMMIT();
    };

    load_stage(0, 0);

    for (int s = 0; s < LIN_STAGES; s++) {
        int d = s & 1;
        if (s + 1 < LIN_STAGES) {
            load_stage(s + 1, (s + 1) & 1);
            CP_WAIT(1);
        } else {
            CP_WAIT(0);
        }
        __syncthreads();

        uint32_t aB = aB0 + d * (128 * LDS_PAD * 2);
        uint32_t bB = bB0 + d * (128 * LDS_PAD * 2);
        #pragma unroll
        for (int ks = 0; ks < 2; ks++) {
            uint32_t a[4][4], b[4][2];
            #pragma unroll
            for (int mi = 0; mi < 4; mi++) {
                int row = warp_m * 64 + mi * 16 + (lane & 15);
                int col = ks * 16 + (lane >> 4) * 8;
                uint32_t ad = aB + (row * LDS_PAD + col) * 2;
                LDSM_X4(a[mi][0], a[mi][1], a[mi][2], a[mi][3], ad);
            }
            #pragma unroll
            for (int ni = 0; ni < 4; ni++) {
                int row = warp_n * 32 + ni * 8 + (lane & 7);
                int col = ks * 16 + ((lane >> 3) & 1) * 8;
                uint32_t bd = bB + (row * LDS_PAD + col) * 2;
                LDSM_X2(b[ni][0], b[ni][1], bd);
            }
            #pragma unroll
            for (int mi = 0; mi < 4; mi++)
                #pragma unroll
                for (int ni = 0; ni < 4; ni++)
                    MMA16816(c[mi][ni][0], c[mi][ni][1], c[mi][ni][2], c[mi][ni][3],
                             a[mi][0], a[mi][1], a[mi][2], a[mi][3],
                             b[ni][0], b[ni][1]);
        }
        __syncthreads();
    }

    #pragma unroll
    for (int mi = 0; mi < 4; mi++) {
        int m = tb0 + warp_m * 64 + mi * 16 + (lane >> 2);
        #pragma unroll
        for (int ni = 0; ni < 4; ni++) {
            int nl = warp_n * 32 + ni * 8 + (lane & 3) * 2;
            int n = v0 + nl;
            if (n < NITEMS) {
                float b0v = bias_s[nl], b1v = bias_s[nl + 1];
                *(float2*)&out[(size_t)m * NITEMS + n] =
                    make_float2(c[mi][ni][0] + b0v, c[mi][ni][1] + b1v);
                *(float2*)&out[(size_t)(m + 8) * NITEMS + n] =
                    make_float2(c[mi][ni][2] + b0v, c[mi][ni][3] + b1v);
            }
        }
    }
}

// ================= l2 norm =================
__global__ void k_l2zero() { if (threadIdx.x < 2) g_l2[threadIdx.x] = 0.f; }

__global__ void k_l2reduce(const float* __restrict__ W_lin, const float* __restrict__ b_lin) {
    __shared__ float sh[256];
    int tid = threadIdx.x;
    int stride = gridDim.x * blockDim.x;
    float sw = 0.f;
    for (size_t i = blockIdx.x * blockDim.x + tid; i < (size_t)NITEMS * KL; i += stride) {
        float v = W_lin[i]; sw += v * v;
    }
    float sb = 0.f;
    for (int i = blockIdx.x * blockDim.x + tid; i < NITEMS; i += stride) {
        float v = b_lin[i]; sb += v * v;
    }
    sh[tid] = sw; __syncthreads();
    for (int s = 128; s > 0; s >>= 1) { if (tid < s) sh[tid] += sh[tid + s]; __syncthreads(); }
    if (tid == 0) atomicAdd(&g_l2[0], sh[0]);
    __syncthreads();
    sh[tid] = sb; __syncthreads();
    for (int s = 128; s > 0; s >>= 1) { if (tid < s) sh[tid] += sh[tid + s]; __syncthreads(); }
    if (tid == 0) atomicAdd(&g_l2[1], sh[0]);
}

__global__ void k_l2final(float* __restrict__ out, int has_scalar) {
    if (has_scalar && threadIdx.x == 0)
        out[NPN] = sqrtf(g_l2[0]) + sqrtf(g_l2[1]);
}

// ================= launch =================
extern "C" void kernel_launch(void* const* d_in, const int* in_sizes, int n_in,
                              void* d_out, int out_size) {
    const int*   act   = (const int*)  d_in[0];
    const float* rew   = (const float*)d_in[1];
    const float* stat  = (const float*)d_in[2];
    const float* hx    = (const float*)d_in[3];
    const float* cx    = (const float*)d_in[4];
    const float* emb   = (const float*)d_in[5];
    const float* W_ih  = (const float*)d_in[6];
    const float* W_hh  = (const float*)d_in[7];
    const float* b_ih  = (const float*)d_in[8];
    const float* b_hh  = (const float*)d_in[9];
    const float* W_lin = (const float*)d_in[10];
    const float* b_lin = (const float*)d_in[11];
    float* out = (float*)d_out;

    const int lstm_smem = LP_SM_FLOATS * (int)sizeof(float);
    cudaFuncSetAttribute(k_lstm_persist,
                         cudaFuncAttributeMaxDynamicSharedMemorySize, lstm_smem);

    k_init<<<(BB * HH + 255) / 256, 256>>>(hx);
    k_ars<<<(TT * BB * 32 + 255) / 256, 256>>>(act, rew, stat, emb);
    k_statsplit<<<(TT * BB * 32 + 255) / 256, 256>>>(stat);
    k_xproj<<<dim3(GG / 128, TT * BB / 128), 256>>>(W_ih, b_ih, b_hh);
    k_splitB<<<(NP * (KP / 4) + 255) / 256, 256>>>(W_lin);

    // all 100 LSTM steps in one persistent launch (128 CTAs, grid barrier)
    k_lstm_persist<<<dim3(64, 2), 256, lstm_smem>>>(W_hh, cx);

    // grid.x = row blocks (fast) so consecutive CTAs share the same B column block
    k_lin_hmma<<<dim3(TT * BB / 128, NP / 128), 256>>>(b_lin, out);

    k_l2zero<<<1, 32>>>();
    k_l2reduce<<<512, 256>>>(W_lin, b_lin);
    k_l2final<<<1, 32>>>(out, out_size > NPN ? 1 : 0);
}

// round 13
// speedup vs baseline: 1.9999x; 1.1000x over previous
#include <cuda_runtime.h>
#include <cuda_bf16.h>
#include <math.h>
#include <stdint.h>

#define TT 100
#define BB 128
#define HH 512
#define GG 2048            // 4*H
#define NIN 128            // rnn input dim
#define NITEMS 10000
#define KL 544             // H + SDIM
#define NPN 128000000      // TT*BB*NITEMS
#define KP 576             // K padded (row stride for split buffers)
#define NP 10240           // items padded to 40*256

// HMMA GEMM config for final linear
#define LIN_STAGES 51      // 3 passes * 544/32
#define PASS_STEPS 17      // 544/32
#define LDS_PAD 40         // 32 data + 8 pad bf16 per smem row

// persistent LSTM config
#define LSTM_CTAS 128
#define HS_STRIDE 66       // h_s k-row stride: EVEN (f32x2 pair alignment)

typedef unsigned long long ull;

// ---------------- static device scratch (no runtime allocation) ----------------
__device__ float g_ars[TT * BB * NIN];
__device__ float g_xproj[TT * BB * GG];
__device__ float g_h[2][BB * HH];
__device__ float g_l2[2];
__device__ unsigned g_barrier;
__device__ __nv_bfloat16 g_Ah[(size_t)TT * BB * KP];
__device__ __nv_bfloat16 g_Al[(size_t)TT * BB * KP];
__device__ __nv_bfloat16 g_Bh[(size_t)NP * KP];
__device__ __nv_bfloat16 g_Bl[(size_t)NP * KP];

// ---------------- f32x2 helpers ----------------
__device__ __forceinline__ ull pack2(float x, float y) {
    ull v; asm("mov.b64 %0,{%1,%2};" : "=l"(v) : "f"(x), "f"(y)); return v;
}
__device__ __forceinline__ float2 unpack2(ull v) {
    float2 f; asm("mov.b64 {%0,%1},%2;" : "=f"(f.x), "=f"(f.y) : "l"(v)); return f;
}
__device__ __forceinline__ void fma2(ull &c, ull a, ull b) {
    asm("fma.rn.f32x2 %0,%1,%2,%3;" : "=l"(c) : "l"(a), "l"(b), "l"(c));
}
__device__ __forceinline__ float sigf(float x) { return 1.0f / (1.0f + expf(-x)); }

__device__ __forceinline__ uint32_t smem_u32(const void* p) {
    uint32_t a;
    asm("{ .reg .u64 t; cvta.to.shared.u64 t, %1; cvt.u32.u64 %0, t; }" : "=r"(a) : "l"(p));
    return a;
}

// ---------------- cp.async / ldmatrix / mma (baseline sm_80 PTX) ----------------
#define CP_ASYNC16(sdst, gsrc) \
    asm volatile("cp.async.cg.shared.global [%0], [%1], 16;" :: "r"(sdst), "l"(gsrc))
#define CP_COMMIT() asm volatile("cp.async.commit_group;" ::: "memory")
#define CP_WAIT(n)  asm volatile("cp.async.wait_group %0;" :: "n"(n) : "memory")

#define LDSM_X4(r0, r1, r2, r3, addr) \
    asm volatile("ldmatrix.sync.aligned.m8n8.x4.shared.b16 {%0,%1,%2,%3}, [%4];" \
        : "=r"(r0), "=r"(r1), "=r"(r2), "=r"(r3) : "r"(addr))

#define MMA16816(c0, c1, c2, c3, a0, a1, a2, a3, b0, b1) \
    asm volatile("mma.sync.aligned.m16n8k16.row.col.f32.bf16.bf16.f32 " \
        "{%0,%1,%2,%3}, {%4,%5,%6,%7}, {%8,%9}, {%0,%1,%2,%3};" \
        : "+f"(c0), "+f"(c1), "+f"(c2), "+f"(c3) \
        : "r"(a0), "r"(a1), "r"(a2), "r"(a3), "r"(b0), "r"(b1))

// ================= init (also resets grid barrier each replay) =================
__global__ void k_init(const float* __restrict__ hx) {
    int i = blockIdx.x * blockDim.x + threadIdx.x;
    if (i < BB * HH) g_h[0][i] = hx[i];
    if (i == 0) g_barrier = 0u;
}

// ================= build ars =================
__global__ void k_ars(const int* __restrict__ act, const float* __restrict__ rew,
                      const float* __restrict__ stat, const float* __restrict__ emb) {
    int idx = blockIdx.x * blockDim.x + threadIdx.x;
    if (idx >= TT * BB * 32) return;
    int tb = idx >> 5;
    int k = (idx & 31) * 4;
    float4 v;
    if (k < 64) {
        v = *(const float4*)&emb[(size_t)act[tb] * 64 + k];
    } else if (k < 96) {
        float r = rew[tb];
        int ri = (int)floorf((32.0f * (2.0f - r)) / 4.0f);
        int kb = k - 64;
        v.x = (ri == kb    ) ? 1.f : 0.f;
        v.y = (ri == kb + 1) ? 1.f : 0.f;
        v.z = (ri == kb + 2) ? 1.f : 0.f;
        v.w = (ri == kb + 3) ? 1.f : 0.f;
    } else {
        v = *(const float4*)&stat[(size_t)tb * 32 + (k - 96)];
    }
    *(float4*)&g_ars[(size_t)tb * NIN + k] = v;
}

// ================= statsplit: A cols 512..543 = split-bf16(stat) =================
__global__ void k_statsplit(const float* __restrict__ stat) {
    int idx = blockIdx.x * blockDim.x + threadIdx.x;   // over 12800*32
    if (idx >= TT * BB * 32) return;
    int tb = idx >> 5, s = idx & 31;
    float v = stat[(size_t)tb * 32 + s];
    __nv_bfloat16 hh = __float2bfloat16(v);
    __nv_bfloat16 hl = __float2bfloat16(v - __bfloat162float(hh));
    size_t o = (size_t)tb * KP + HH + s;
    g_Ah[o] = hh;
    g_Al[o] = hl;
}

// ================= x_proj (unchanged, known passing) ==================
__global__ __launch_bounds__(256, 2) void k_xproj(
    const float* __restrict__ W_ih, const float* __restrict__ b_ih,
    const float* __restrict__ b_hh)
{
    __shared__ __align__(16) float A_s[8][132];
    __shared__ __align__(16) float B2_s[8][264];
    const int tid = threadIdx.x;
    const int g0  = blockIdx.x * 128;
    const int tb0 = blockIdx.y * 128;
    const int tx = tid & 15;
    const int ty = tid >> 4;
    const int mf = tid >> 1;
    const int kf = (tid & 1) * 4;

    ull acc[4][8];
    #pragma unroll
    for (int i = 0; i < 4; i++)
        #pragma unroll
        for (int j = 0; j < 8; j++) acc[i][j] = 0ull;

    float4 rA = *(const float4*)&g_ars[(size_t)(tb0 + mf) * NIN + kf];
    float4 rB = *(const float4*)&W_ih[(size_t)(g0 + mf) * NIN + kf];

    for (int kt = 0; kt < NIN / 8; kt++) {
        A_s[kf + 0][mf] = rA.x; A_s[kf + 1][mf] = rA.y;
        A_s[kf + 2][mf] = rA.z; A_s[kf + 3][mf] = rA.w;
        *(ull*)&B2_s[kf + 0][2 * mf] = pack2(rB.x, rB.x);
        *(ull*)&B2_s[kf + 1][2 * mf] = pack2(rB.y, rB.y);
        *(ull*)&B2_s[kf + 2][2 * mf] = pack2(rB.z, rB.z);
        *(ull*)&B2_s[kf + 3][2 * mf] = pack2(rB.w, rB.w);
        __syncthreads();
        if (kt + 1 < NIN / 8) {
            int k0n = (kt + 1) * 8;
            rA = *(const float4*)&g_ars[(size_t)(tb0 + mf) * NIN + k0n + kf];
            rB = *(const float4*)&W_ih[(size_t)(g0 + mf) * NIN + k0n + kf];
        }
        #pragma unroll
        for (int k = 0; k < 8; k++) {
            ulonglong2 a01 = *(const ulonglong2*)&A_s[k][tx * 8];
            ulonglong2 a23 = *(const ulonglong2*)&A_s[k][tx * 8 + 4];
            ull a[4] = {a01.x, a01.y, a23.x, a23.y};
            #pragma unroll
            for (int jh = 0; jh < 2; jh++) {
                ulonglong2 b01 = *(const ulonglong2*)&B2_s[k][ty * 16 + jh * 8];
                ulonglong2 b23 = *(const ulonglong2*)&B2_s[k][ty * 16 + jh * 8 + 4];
                ull b[4] = {b01.x, b01.y, b23.x, b23.y};
                #pragma unroll
                for (int i = 0; i < 4; i++)
                    #pragma unroll
                    for (int j = 0; j < 4; j++)
                        fma2(acc[i][jh * 4 + j], a[i], b[j]);
            }
        }
        __syncthreads();
    }
    float bs[8];
    #pragma unroll
    for (int j = 0; j < 8; j++) {
        int g = g0 + ty * 8 + j;
        bs[j] = b_ih[g] + b_hh[g];
    }
    #pragma unroll
    for (int rp = 0; rp < 4; rp++) {
        float lo[8], hi[8];
        #pragma unroll
        for (int j = 0; j < 8; j++) {
            float2 c = unpack2(acc[rp][j]);
            lo[j] = c.x + bs[j]; hi[j] = c.y + bs[j];
        }
        int row = tb0 + tx * 8 + rp * 2;
        size_t o0 = (size_t)row * GG + g0 + ty * 8;
        *(float4*)&g_xproj[o0]          = make_float4(lo[0], lo[1], lo[2], lo[3]);
        *(float4*)&g_xproj[o0 + 4]      = make_float4(lo[4], lo[5], lo[6], lo[7]);
        *(float4*)&g_xproj[o0 + GG]     = make_float4(hi[0], hi[1], hi[2], hi[3]);
        *(float4*)&g_xproj[o0 + GG + 4] = make_float4(hi[4], hi[5], hi[6], hi[7]);
    }
}

// ================= persistent LSTM (pipelined h staging, prefetched gates) ======
// Grid (64,2) = 128 CTAs: bx -> 8 h-units, by -> 64 batch rows. W_hh slice cached
// once in SMEM (f32x2-dup). Double-buffered h chunks: single sync per chunk, next
// chunk's global loads issued before compute. Cell state in registers.
#define LP_WD_SZ   (512 * 64)
#define LP_HS_OFF  LP_WD_SZ
#define LP_HS_SZ   (32 * HS_STRIDE)
#define LP_GS_OFF  (LP_HS_OFF + 2 * LP_HS_SZ + 2)
#define LP_SM_FLOATS (LP_GS_OFF + 64 * 33 + 4)

__global__ __launch_bounds__(256) void k_lstm_persist(
    const float* __restrict__ W_hh, const float* __restrict__ cx)
{
    extern __shared__ __align__(16) float smf[];
    float* Wd   = smf;               // [k 0..511][32 cols dup'd -> 64 floats]
    float* h_sb = smf + LP_HS_OFF;   // 2 buffers of [k 0..31][r 0..63], stride 66
    float* gs   = smf + LP_GS_OFF;   // [r 0..63][c 0..31], stride 33

    const int tid = threadIdx.x;
    const int m0 = blockIdx.x * 8;
    const int r0 = blockIdx.y * 64;
    const int tx = tid & 15;
    const int ty = tid >> 4;
    const int lr  = tid >> 3,  lk4  = tid & 7;          // staging row/k4 (first half)
    const int lr2 = (tid + 256) >> 3, lk42 = tid & 7;   // second half (idx+256)

    // one-time: cache W slice, duplicated for f32x2
    #pragma unroll
    for (int it = 0; it < 16; it++) {
        int idx = tid + it * 256;
        int c = idx >> 7;
        int k4 = idx & 127;
        int grow = (c >> 3) * HH + m0 + (c & 7);
        float4 v = *(const float4*)&W_hh[(size_t)grow * HH + k4 * 4];
        *(ull*)&Wd[(size_t)(k4 * 4 + 0) * 64 + 2 * c] = pack2(v.x, v.x);
        *(ull*)&Wd[(size_t)(k4 * 4 + 1) * 64 + 2 * c] = pack2(v.y, v.y);
        *(ull*)&Wd[(size_t)(k4 * 4 + 2) * 64 + 2 * c] = pack2(v.z, v.z);
        *(ull*)&Wd[(size_t)(k4 * 4 + 3) * 64 + 2 * c] = pack2(v.w, v.w);
    }

    float creg[2];
    #pragma unroll
    for (int e = 0; e < 2; e++) {
        int p = tid * 2 + e;
        creg[e] = cx[(size_t)(r0 + (p >> 3)) * HH + m0 + (p & 7)];
    }

    const int c0 = 2 * ty, c1 = 2 * ty + 1;
    const int gcol0 = (c0 >> 3) * HH + m0 + (c0 & 7);
    const int gcol1 = (c1 >> 3) * HH + m0 + (c1 & 7);
    __syncthreads();

    for (int t = 0; t < TT; t++) {
        const float* __restrict__ hsrc = g_h[t & 1];
        float* __restrict__ hdst = g_h[(t + 1) & 1];

        // prefetch xproj gate terms (consumed after the GEMM)
        float xv[2][2][2];   // [pi][col][row-in-pair]
        #pragma unroll
        for (int pi = 0; pi < 2; pi++) {
            int r = pi * 32 + 2 * tx;
            size_t base = ((size_t)t * BB + r0 + r) * GG;
            xv[pi][0][0] = g_xproj[base + gcol0];
            xv[pi][0][1] = g_xproj[base + GG + gcol0];
            xv[pi][1][0] = g_xproj[base + gcol1];
            xv[pi][1][1] = g_xproj[base + GG + gcol1];
        }

        ull acc[2][2];
        acc[0][0] = acc[0][1] = acc[1][0] = acc[1][1] = 0ull;

        // preload chunk 0 into registers
        float4 rv0 = *(const float4*)&hsrc[(size_t)(r0 + lr) * HH + lk4 * 4];
        float4 rv1 = *(const float4*)&hsrc[(size_t)(r0 + lr2) * HH + lk42 * 4];

        for (int ch = 0; ch < 16; ch++) {
            float* hb = h_sb + (ch & 1) * LP_HS_SZ;
            hb[(lk4 * 4 + 0) * HS_STRIDE + lr] = rv0.x;
            hb[(lk4 * 4 + 1) * HS_STRIDE + lr] = rv0.y;
            hb[(lk4 * 4 + 2) * HS_STRIDE + lr] = rv0.z;
            hb[(lk4 * 4 + 3) * HS_STRIDE + lr] = rv0.w;
            hb[(lk42 * 4 + 0) * HS_STRIDE + lr2] = rv1.x;
            hb[(lk42 * 4 + 1) * HS_STRIDE + lr2] = rv1.y;
            hb[(lk42 * 4 + 2) * HS_STRIDE + lr2] = rv1.z;
            hb[(lk42 * 4 + 3) * HS_STRIDE + lr2] = rv1.w;
            __syncthreads();
            if (ch < 15) {
                int kn = (ch + 1) * 32;
                rv0 = *(const float4*)&hsrc[(size_t)(r0 + lr) * HH + kn + lk4 * 4];
                rv1 = *(const float4*)&hsrc[(size_t)(r0 + lr2) * HH + kn + lk42 * 4];
            }
            int kk0 = ch * 32;
            #pragma unroll
            for (int k = 0; k < 32; k++) {
                ull a0 = *(const ull*)&hb[k * HS_STRIDE + 2 * tx];
                ull a1 = *(const ull*)&hb[k * HS_STRIDE + 32 + 2 * tx];
                ulonglong2 b = *(const ulonglong2*)&Wd[(size_t)(kk0 + k) * 64 + ty * 4];
                fma2(acc[0][0], a0, b.x); fma2(acc[0][1], a0, b.y);
                fma2(acc[1][0], a1, b.x); fma2(acc[1][1], a1, b.y);
            }
        }

        // gates = acc + prefetched xproj -> gs (own cells; no pre-sync needed)
        #pragma unroll
        for (int pi = 0; pi < 2; pi++) {
            float2 v0 = unpack2(acc[pi][0]);
            float2 v1 = unpack2(acc[pi][1]);
            int r = pi * 32 + 2 * tx;
            gs[r * 33 + c0]       = v0.x + xv[pi][0][0];
            gs[(r + 1) * 33 + c0] = v0.y + xv[pi][0][1];
            gs[r * 33 + c1]       = v1.x + xv[pi][1][0];
            gs[(r + 1) * 33 + c1] = v1.y + xv[pi][1][1];
        }
        __syncthreads();

        // cell update + h writes (fp32 ping-pong + split-bf16 A operand)
        #pragma unroll
        for (int e = 0; e < 2; e++) {
            int p = tid * 2 + e;
            int r = p >> 3, mi = p & 7;
            float gi = gs[r * 33 + mi];
            float gf = gs[r * 33 + 8 + mi];
            float gg = gs[r * 33 + 16 + mi];
            float go = gs[r * 33 + 24 + mi];
            float cn = sigf(gf) * creg[e] + sigf(gi) * tanhf(gg);
            float h = sigf(go) * tanhf(cn);
            creg[e] = cn;
            hdst[(size_t)(r0 + r) * HH + m0 + mi] = h;
            __nv_bfloat16 hh = __float2bfloat16(h);
            __nv_bfloat16 hl = __float2bfloat16(h - __bfloat162float(hh));
            size_t ao = ((size_t)t * BB + r0 + r) * KP + m0 + mi;
            g_Ah[ao] = hh;
            g_Al[ao] = hl;
        }

        // grid barrier (post-spin threadfence -> CCTL.IVALL keeps g_h reads fresh)
        __syncthreads();
        if (tid == 0) {
            __threadfence();
            atomicAdd(&g_barrier, 1u);
            unsigned tgt = (unsigned)(t + 1) * LSTM_CTAS;
            while (*(volatile unsigned*)&g_barrier < tgt) { }
            __threadfence();
        }
        __syncthreads();
    }
}

// ================= bf16 hi/lo split of W_lin =================
__global__ void k_splitB(const float* __restrict__ W) {
    int idx = blockIdx.x * blockDim.x + threadIdx.x;   // over NP * (KP/4)
    if (idx >= NP * (KP / 4)) return;
    int row = idx / (KP / 4);
    int c4 = (idx % (KP / 4)) * 4;
    float v[4] = {0.f, 0.f, 0.f, 0.f};
    if (row < NITEMS) {
        #pragma unroll
        for (int j = 0; j < 4; j++) {
            int c = c4 + j;
            if (c < KL) v[j] = W[(size_t)row * KL + c];
        }
    }
    __nv_bfloat16 h[4], l[4];
    #pragma unroll
    for (int j = 0; j < 4; j++) {
        h[j] = __float2bfloat16(v[j]);
        l[j] = __float2bfloat16(v[j] - __bfloat162float(h[j]));
    }
    size_t o = (size_t)row * KP + c4;
    *(__nv_bfloat162*)&g_Bh[o]     = __nv_bfloat162(h[0], h[1]);
    *(__nv_bfloat162*)&g_Bh[o + 2] = __nv_bfloat162(h[2], h[3]);
    *(__nv_bfloat162*)&g_Bl[o]     = __nv_bfloat162(l[0], l[1]);
    *(__nv_bfloat162*)&g_Bl[o + 2] = __nv_bfloat162(l[2], l[3]);
}

// ================= final linear via mma.sync bf16, CTA 128x256 ==================
// 8 warps as 2x4, warp tile 64x64 (4x8 MMA tiles), BK=32, cp.async double buffer.
// K_eff = 1632: stage s -> pass p=s/17 (Ah*Bh, Al*Bh, Ah*Bl), kk=(s%17)*32.
#define LIN_A_BYTES (128 * LDS_PAD * 2)
#define LIN_B_BYTES (256 * LDS_PAD * 2)
#define LIN_SM_BYTES (2 * LIN_A_BYTES + 2 * LIN_B_BYTES + 256 * 4)

__global__ __launch_bounds__(256) void k_lin_hmma(const float* __restrict__ b_lin,
                                                  float* __restrict__ out)
{
    extern __shared__ __align__(16) char lsm[];
    __nv_bfloat16* As = (__nv_bfloat16*)lsm;                          // 2 buffers
    __nv_bfloat16* Bs = (__nv_bfloat16*)(lsm + 2 * LIN_A_BYTES);      // 2 buffers
    float* bias_s = (float*)(lsm + 2 * LIN_A_BYTES + 2 * LIN_B_BYTES);

    const int tid = threadIdx.x;
    const int lane = tid & 31;
    const int wid = tid >> 5;
    const int warp_m = wid & 1;        // 0..1 -> m offset *64
    const int warp_n = wid >> 1;       // 0..3 -> n offset *64
    const int tb0 = blockIdx.x * 128;  // row block (fast dim -> B reuse in L2)
    const int v0  = blockIdx.y * 256;  // item block

    {
        int v = v0 + tid;
        bias_s[tid] = (v < NITEMS) ? b_lin[v] : 0.f;
    }

    const uint32_t aB0 = smem_u32(As);
    const uint32_t bB0 = smem_u32(Bs);

    float c[4][8][4];
    #pragma unroll
    for (int mi = 0; mi < 4; mi++)
        #pragma unroll
        for (int ni = 0; ni < 8; ni++)
            #pragma unroll
            for (int e = 0; e < 4; e++) c[mi][ni][e] = 0.f;

    auto load_stage = [&](int s, int d) {
        int p = s / PASS_STEPS;
        int kk = (s % PASS_STEPS) * 32;
        const __nv_bfloat16* Asrc = ((p == 1) ? g_Al : g_Ah) + (size_t)tb0 * KP + kk;
        const __nv_bfloat16* Bsrc = ((p == 2) ? g_Bl : g_Bh) + (size_t)v0  * KP + kk;
        uint32_t aB = aB0 + d * LIN_A_BYTES;
        uint32_t bB = bB0 + d * LIN_B_BYTES;
        #pragma unroll
        for (int it = 0; it < 2; it++) {           // A: 512 chunks
            int idx = tid + it * 256;
            int r = idx >> 2, c16 = idx & 3;
            CP_ASYNC16(aB + (r * LDS_PAD + c16 * 8) * 2,
                       (const char*)(Asrc + (size_t)r * KP + c16 * 8));
        }
        #pragma unroll
        for (int it = 0; it < 4; it++) {           // B: 1024 chunks
            int idx = tid + it * 256;
            int r = idx >> 2, c16 = idx & 3;
            CP_ASYNC16(bB + (r * LDS_PAD + c16 * 8) * 2,
                       (const char*)(Bsrc + (size_t)r * KP + c16 * 8));
        }
        CP_COMMIT();
    };

    load_stage(0, 0);

    for (int s = 0; s < LIN_STAGES; s++) {
        int d = s & 1;
        if (s + 1 < LIN_STAGES) {
            load_stage(s + 1, (s + 1) & 1);
            CP_WAIT(1);
        } else {
            CP_WAIT(0);
        }
        __syncthreads();

        uint32_t aB = aB0 + d * LIN_A_BYTES;
        uint32_t bB = bB0 + d * LIN_B_BYTES;
        #pragma unroll
        for (int ks = 0; ks < 2; ks++) {
            uint32_t a[4][4], b[8][2];
            #pragma unroll
            for (int mi = 0; mi < 4; mi++) {
                int row = warp_m * 64 + mi * 16 + (lane & 15);
                int col = ks * 16 + (lane >> 4) * 8;
                LDSM_X4(a[mi][0], a[mi][1], a[mi][2], a[mi][3],
                        aB + (row * LDS_PAD + col) * 2);
            }
            #pragma unroll
            for (int q = 0; q < 4; q++) {
                int row = warp_n * 64 + q * 16 + (lane & 7) + ((lane >> 4) & 1) * 8;
                int col = ks * 16 + ((lane >> 3) & 1) * 8;
                LDSM_X4(b[2 * q][0], b[2 * q][1], b[2 * q + 1][0], b[2 * q + 1][1],
                        bB + (row * LDS_PAD + col) * 2);
            }
            #pragma unroll
            for (int mi = 0; mi < 4; mi++)
                #pragma unroll
                for (int ni = 0; ni < 8; ni++)
                    MMA16816(c[mi][ni][0], c[mi][ni][1], c[mi][ni][2], c[mi][ni][3],
                             a[mi][0], a[mi][1], a[mi][2], a[mi][3],
                             b[ni][0], b[ni][1]);
        }
        __syncthreads();
    }

    // epilogue: direct float2 stores with bias
    #pragma unroll
    for (int mi = 0; mi < 4; mi++) {
        int m = tb0 + warp_m * 64 + mi * 16 + (lane >> 2);
        #pragma unroll
        for (int ni = 0; ni < 8; ni++) {
            int nl = warp_n * 64 + ni * 8 + (lane & 3) * 2;
            int n = v0 + nl;
            if (n < NITEMS) {
                float b0v = bias_s[nl], b1v = bias_s[nl + 1];
                *(float2*)&out[(size_t)m * NITEMS + n] =
                    make_float2(c[mi][ni][0] + b0v, c[mi][ni][1] + b1v);
                *(float2*)&out[(size_t)(m + 8) * NITEMS + n] =
                    make_float2(c[mi][ni][2] + b0v, c[mi][ni][3] + b1v);
            }
        }
    }
}

// ================= l2 norm =================
__global__ void k_l2zero() { if (threadIdx.x < 2) g_l2[threadIdx.x] = 0.f; }

__global__ void k_l2reduce(const float* __restrict__ W_lin, const float* __restrict__ b_lin) {
    __shared__ float sh[256];
    int tid = threadIdx.x;
    int stride = gridDim.x * blockDim.x;
    float sw = 0.f;
    for (size_t i = blockIdx.x * blockDim.x + tid; i < (size_t)NITEMS * KL; i += stride) {
        float v = W_lin[i]; sw += v * v;
    }
    float sb = 0.f;
    for (int i = blockIdx.x * blockDim.x + tid; i < NITEMS; i += stride) {
        float v = b_lin[i]; sb += v * v;
    }
    sh[tid] = sw; __syncthreads();
    for (int s = 128; s > 0; s >>= 1) { if (tid < s) sh[tid] += sh[tid + s]; __syncthreads(); }
    if (tid == 0) atomicAdd(&g_l2[0], sh[0]);
    __syncthreads();
    sh[tid] = sb; __syncthreads();
    for (int s = 128; s > 0; s >>= 1) { if (tid < s) sh[tid] += sh[tid + s]; __syncthreads(); }
    if (tid == 0) atomicAdd(&g_l2[1], sh[0]);
}

__global__ void k_l2final(float* __restrict__ out, int has_scalar) {
    if (has_scalar && threadIdx.x == 0)
        out[NPN] = sqrtf(g_l2[0]) + sqrtf(g_l2[1]);
}

// ================= launch =================
extern "C" void kernel_launch(void* const* d_in, const int* in_sizes, int n_in,
                              void* d_out, int out_size) {
    const int*   act   = (const int*)  d_in[0];
    const float* rew   = (const float*)d_in[1];
    const float* stat  = (const float*)d_in[2];
    const float* hx    = (const float*)d_in[3];
    const float* cx    = (const float*)d_in[4];
    const float* emb   = (const float*)d_in[5];
    const float* W_ih  = (const float*)d_in[6];
    const float* W_hh  = (const float*)d_in[7];
    const float* b_ih  = (const float*)d_in[8];
    const float* b_hh  = (const float*)d_in[9];
    const float* W_lin = (const float*)d_in[10];
    const float* b_lin = (const float*)d_in[11];
    float* out = (float*)d_out;

    const int lstm_smem = LP_SM_FLOATS * (int)sizeof(float);
    cudaFuncSetAttribute(k_lstm_persist,
                         cudaFuncAttributeMaxDynamicSharedMemorySize, lstm_smem);
    cudaFuncSetAttribute(k_lin_hmma,
                         cudaFuncAttributeMaxDynamicSharedMemorySize, LIN_SM_BYTES);

    k_init<<<(BB * HH + 255) / 256, 256>>>(hx);
    k_ars<<<(TT * BB * 32 + 255) / 256, 256>>>(act, rew, stat, emb);
    k_statsplit<<<(TT * BB * 32 + 255) / 256, 256>>>(stat);
    k_xproj<<<dim3(GG / 128, TT * BB / 128), 256>>>(W_ih, b_ih, b_hh);
    k_splitB<<<(NP * (KP / 4) + 255) / 256, 256>>>(W_lin);

    // all 100 LSTM steps in one persistent launch (128 CTAs, grid barrier)
    k_lstm_persist<<<dim3(64, 2), 256, lstm_smem>>>(W_hh, cx);

    // grid.x = row blocks (fast) so consecutive CTAs share the same B column block
    k_lin_hmma<<<dim3(TT * BB / 128, NP / 256), 256, LIN_SM_BYTES>>>(b_lin, out);

    k_l2zero<<<1, 32>>>();
    k_l2reduce<<<512, 256>>>(W_lin, b_lin);
    k_l2final<<<1, 32>>>(out, out_size > NPN ? 1 : 0);
}